// round 3
// baseline (speedup 1.0000x reference)
#include <cuda_runtime.h>
#include <math.h>

#define B_  2
#define L_  2048
#define S_  2048
#define D_  256
#define H_  8
#define HD_ 32
#define ROWS (B_*L_)   // 4096

// ---------------- scratch (no allocations allowed) ----------------
__device__ float g_Q  [B_*L_*D_];
__device__ float g_K  [B_*S_*D_];
__device__ float g_V  [B_*S_*D_];
__device__ float g_O  [B_*L_*D_];
__device__ float g_M1 [B_*L_*D_];
__device__ float g_Hin[B_*L_*2*D_];
__device__ float g_Hre[B_*L_*2*D_];
__device__ float g_M2 [B_*L_*D_];

// ---------------- generic NT GEMM: C[M,N] = A[M,K] @ B[N,K]^T ----------------
// 64x64 block tile, 256 threads, 4x4 micro-tile, BK=32. All dims divide evenly.
__global__ void __launch_bounds__(256) gemm_nt(const float* __restrict__ A,
                                               const float* __restrict__ Bw,
                                               float* __restrict__ C,
                                               int M, int N, int K, int relu) {
    __shared__ float As[32][68];
    __shared__ float Bs[32][68];
    const int tid = threadIdx.x;
    const int m0 = blockIdx.y * 64;
    const int n0 = blockIdx.x * 64;
    const int tx = tid & 15, ty = tid >> 4;
    float acc[4][4];
#pragma unroll
    for (int i = 0; i < 4; i++)
#pragma unroll
        for (int j = 0; j < 4; j++) acc[i][j] = 0.f;

    for (int k0 = 0; k0 < K; k0 += 32) {
#pragma unroll
        for (int it = 0; it < 2; it++) {
            int idx = tid + it * 256;
            int r = idx >> 3, c = idx & 7;
            float4 a = *(const float4*)(A  + (size_t)(m0 + r) * K + k0 + 4 * c);
            As[4*c+0][r] = a.x; As[4*c+1][r] = a.y; As[4*c+2][r] = a.z; As[4*c+3][r] = a.w;
            float4 w = *(const float4*)(Bw + (size_t)(n0 + r) * K + k0 + 4 * c);
            Bs[4*c+0][r] = w.x; Bs[4*c+1][r] = w.y; Bs[4*c+2][r] = w.z; Bs[4*c+3][r] = w.w;
        }
        __syncthreads();
#pragma unroll
        for (int k = 0; k < 32; k++) {
            float4 a = *(const float4*)&As[k][ty * 4];
            float4 b = *(const float4*)&Bs[k][tx * 4];
            acc[0][0] += a.x*b.x; acc[0][1] += a.x*b.y; acc[0][2] += a.x*b.z; acc[0][3] += a.x*b.w;
            acc[1][0] += a.y*b.x; acc[1][1] += a.y*b.y; acc[1][2] += a.y*b.z; acc[1][3] += a.y*b.w;
            acc[2][0] += a.z*b.x; acc[2][1] += a.z*b.y; acc[2][2] += a.z*b.z; acc[2][3] += a.z*b.w;
            acc[3][0] += a.w*b.x; acc[3][1] += a.w*b.y; acc[3][2] += a.w*b.z; acc[3][3] += a.w*b.w;
        }
        __syncthreads();
    }
#pragma unroll
    for (int i = 0; i < 4; i++) {
        float4 o;
        o.x = acc[i][0]; o.y = acc[i][1]; o.z = acc[i][2]; o.w = acc[i][3];
        if (relu) {
            o.x = fmaxf(o.x, 0.f); o.y = fmaxf(o.y, 0.f);
            o.z = fmaxf(o.z, 0.f); o.w = fmaxf(o.w, 0.f);
        }
        *(float4*)(C + (size_t)(m0 + ty * 4 + i) * N + n0 + tx * 4) = o;
    }
}

// ---------------- flash attention with elementwise attn_factor ----------------
// grid (L/128, B*H), 128 threads; thread t owns query row q0+t of head (b,h).
// K/V smem reads are warp-uniform (broadcast) -> smem crossbar is not the bottleneck.
__global__ void __launch_bounds__(128) attn_kernel(const float* __restrict__ Q,
                                                   const float* __restrict__ K,
                                                   const float* __restrict__ V,
                                                   const float* __restrict__ AF,
                                                   float* __restrict__ O) {
    __shared__ float4 Ks4[32][8];
    __shared__ float4 Vs4[32][8];
    __shared__ float  AFs[128][33];
    const int b  = blockIdx.y >> 3;   // H = 8
    const int h  = blockIdx.y & 7;
    const int q0 = blockIdx.x * 128;
    const int tid = threadIdx.x;
    const float scale = 0.17677669529663687f;  // 1/sqrt(32)

    const float* qptr = Q + ((size_t)(b * L_ + q0 + tid)) * D_ + h * HD_;
    float q[32];
#pragma unroll
    for (int c = 0; c < 8; c++) {
        float4 t = *(const float4*)(qptr + 4 * c);
        q[4*c] = t.x; q[4*c+1] = t.y; q[4*c+2] = t.z; q[4*c+3] = t.w;
    }
    float m = -3.0e38f, l = 0.f;
    float acc[32];
#pragma unroll
    for (int d = 0; d < 32; d++) acc[d] = 0.f;

    const float* afbase = AF + ((size_t)b * L_ + q0) * S_;

    for (int s0 = 0; s0 < S_; s0 += 32) {
#pragma unroll
        for (int it = 0; it < 2; it++) {
            int idx = tid + it * 128;
            int j = idx >> 3, c = idx & 7;
            Ks4[j][c] = *(const float4*)(K + ((size_t)(b * S_ + s0 + j)) * D_ + h * HD_ + 4 * c);
            Vs4[j][c] = *(const float4*)(V + ((size_t)(b * S_ + s0 + j)) * D_ + h * HD_ + 4 * c);
        }
#pragma unroll
        for (int it = 0; it < 8; it++) {
            int idx = tid + it * 128;
            int r = idx >> 3, c = idx & 7;
            float4 v = *(const float4*)(afbase + (size_t)r * S_ + s0 + 4 * c);
            AFs[r][4*c] = v.x; AFs[r][4*c+1] = v.y; AFs[r][4*c+2] = v.z; AFs[r][4*c+3] = v.w;
        }
        __syncthreads();

        float sc[32];
        float tmax = -3.0e38f;
#pragma unroll
        for (int j = 0; j < 32; j++) {
            float s = 0.f;
#pragma unroll
            for (int c = 0; c < 8; c++) {
                float4 kk = Ks4[j][c];
                s += q[4*c] * kk.x + q[4*c+1] * kk.y + q[4*c+2] * kk.z + q[4*c+3] * kk.w;
            }
            s = s * scale * AFs[tid][j];
            sc[j] = s;
            tmax = fmaxf(tmax, s);
        }
        float m_new = fmaxf(m, tmax);
        float corr = __expf(m - m_new);
        float psum = 0.f;
#pragma unroll
        for (int j = 0; j < 32; j++) { float p = __expf(sc[j] - m_new); sc[j] = p; psum += p; }
        l = l * corr + psum;
        m = m_new;
#pragma unroll
        for (int d = 0; d < 32; d++) acc[d] *= corr;
#pragma unroll
        for (int j = 0; j < 32; j++) {
            float p = sc[j];
#pragma unroll
            for (int c = 0; c < 8; c++) {
                float4 vv = Vs4[j][c];
                acc[4*c]   += p * vv.x;
                acc[4*c+1] += p * vv.y;
                acc[4*c+2] += p * vv.z;
                acc[4*c+3] += p * vv.w;
            }
        }
        __syncthreads();
    }
    float inv = 1.f / l;
    float* optr = O + ((size_t)(b * L_ + q0 + tid)) * D_ + h * HD_;
#pragma unroll
    for (int c = 0; c < 8; c++) {
        float4 t;
        t.x = acc[4*c] * inv; t.y = acc[4*c+1] * inv;
        t.z = acc[4*c+2] * inv; t.w = acc[4*c+3] * inv;
        *(float4*)(optr + 4 * c) = t;
    }
}

// ---------------- LN1 fused with concat materialization ----------------
// Hin[row, 0:256] = x[row], Hin[row, 256:512] = LN(M1[row])
__global__ void __launch_bounds__(256) ln_concat_kernel(const float* __restrict__ M1,
                                                        const float* __restrict__ x,
                                                        const float* __restrict__ g,
                                                        const float* __restrict__ b,
                                                        float* __restrict__ Hin) {
    int warp = threadIdx.x >> 5, lane = threadIdx.x & 31;
    int row = blockIdx.x * 8 + warp;
    const float* p = M1 + (size_t)row * D_;
    float v[8]; float s = 0.f;
#pragma unroll
    for (int k = 0; k < 8; k++) { v[k] = p[lane + 32 * k]; s += v[k]; }
#pragma unroll
    for (int o = 16; o; o >>= 1) s += __shfl_xor_sync(0xffffffffu, s, o);
    float mean = s * (1.f / 256.f);
    float vs = 0.f;
#pragma unroll
    for (int k = 0; k < 8; k++) { float d = v[k] - mean; vs += d * d; }
#pragma unroll
    for (int o = 16; o; o >>= 1) vs += __shfl_xor_sync(0xffffffffu, vs, o);
    float rstd = rsqrtf(vs * (1.f / 256.f) + 1e-5f);
    float* ho = Hin + (size_t)row * (2 * D_);
    const float* xr = x + (size_t)row * D_;
#pragma unroll
    for (int k = 0; k < 8; k++) {
        int col = lane + 32 * k;
        ho[col]      = xr[col];
        ho[D_ + col] = (v[k] - mean) * rstd * g[col] + b[col];
    }
}

// ---------------- LN2 + residual, writes final output ----------------
__global__ void __launch_bounds__(256) ln_residual_kernel(const float* __restrict__ M2,
                                                          const float* __restrict__ x,
                                                          const float* __restrict__ g,
                                                          const float* __restrict__ b,
                                                          float* __restrict__ out) {
    int warp = threadIdx.x >> 5, lane = threadIdx.x & 31;
    int row = blockIdx.x * 8 + warp;
    const float* p = M2 + (size_t)row * D_;
    float v[8]; float s = 0.f;
#pragma unroll
    for (int k = 0; k < 8; k++) { v[k] = p[lane + 32 * k]; s += v[k]; }
#pragma unroll
    for (int o = 16; o; o >>= 1) s += __shfl_xor_sync(0xffffffffu, s, o);
    float mean = s * (1.f / 256.f);
    float vs = 0.f;
#pragma unroll
    for (int k = 0; k < 8; k++) { float d = v[k] - mean; vs += d * d; }
#pragma unroll
    for (int o = 16; o; o >>= 1) vs += __shfl_xor_sync(0xffffffffu, vs, o);
    float rstd = rsqrtf(vs * (1.f / 256.f) + 1e-5f);
    const float* xr = x + (size_t)row * D_;
    float* orow = out + (size_t)row * D_;
#pragma unroll
    for (int k = 0; k < 8; k++) {
        int col = lane + 32 * k;
        orow[col] = xr[col] + (v[k] - mean) * rstd * g[col] + b[col];
    }
}

// ---------------- launch ----------------
extern "C" void kernel_launch(void* const* d_in, const int* in_sizes, int n_in,
                              void* d_out, int out_size) {
    const float* x   = (const float*)d_in[0];
    const float* src = (const float*)d_in[1];
    const float* af  = (const float*)d_in[2];
    const float* Wq  = (const float*)d_in[3];
    const float* Wk  = (const float*)d_in[4];
    const float* Wv  = (const float*)d_in[5];
    const float* Wm  = (const float*)d_in[6];
    const float* W1  = (const float*)d_in[7];
    const float* W2  = (const float*)d_in[8];
    const float* g1  = (const float*)d_in[9];
    const float* b1  = (const float*)d_in[10];
    const float* g2  = (const float*)d_in[11];
    const float* b2  = (const float*)d_in[12];
    float* out = (float*)d_out;

    float *Qp, *Kp, *Vp, *Op, *M1p, *Hin, *Hre, *M2p;
    cudaGetSymbolAddress((void**)&Qp,  g_Q);
    cudaGetSymbolAddress((void**)&Kp,  g_K);
    cudaGetSymbolAddress((void**)&Vp,  g_V);
    cudaGetSymbolAddress((void**)&Op,  g_O);
    cudaGetSymbolAddress((void**)&M1p, g_M1);
    cudaGetSymbolAddress((void**)&Hin, g_Hin);
    cudaGetSymbolAddress((void**)&Hre, g_Hre);
    cudaGetSymbolAddress((void**)&M2p, g_M2);

    dim3 blk(256);
    // Q/K/V projections: [4096,256] = [4096,256] @ [256,256]^T
    gemm_nt<<<dim3(D_ / 64, ROWS / 64), blk>>>(x,   Wq, Qp, ROWS, D_, D_, 0);
    gemm_nt<<<dim3(D_ / 64, ROWS / 64), blk>>>(src, Wk, Kp, ROWS, D_, D_, 0);
    gemm_nt<<<dim3(D_ / 64, ROWS / 64), blk>>>(src, Wv, Vp, ROWS, D_, D_, 0);
    // fused attention (QK^T * scale * attn_factor -> softmax -> AV)
    attn_kernel<<<dim3(L_ / 128, B_ * H_), 128>>>(Qp, Kp, Vp, af, Op);
    // message = O @ Wm^T
    gemm_nt<<<dim3(D_ / 64, ROWS / 64), blk>>>(Op, Wm, M1p, ROWS, D_, D_, 0);
    // LN1 + concat [x, ln(message)]
    ln_concat_kernel<<<ROWS / 8, 256>>>(M1p, x, g1, b1, Hin);
    // h = relu(Hin @ W1^T)  [4096,512]
    gemm_nt<<<dim3(2 * D_ / 64, ROWS / 64), blk>>>(Hin, W1, Hre, ROWS, 2 * D_, 2 * D_, 1);
    // M2 = h @ W2^T  [4096,256]
    gemm_nt<<<dim3(D_ / 64, ROWS / 64), blk>>>(Hre, W2, M2p, ROWS, D_, 2 * D_, 0);
    // out = x + LN2(M2)
    ln_residual_kernel<<<ROWS / 8, 256>>>(M2p, x, g2, b2, out);
}

// round 4
// speedup vs baseline: 1.1863x; 1.1863x over previous
#include <cuda_runtime.h>
#include <math.h>

#define B_  2
#define L_  2048
#define S_  2048
#define D_  256
#define H_  8
#define HD_ 32
#define ROWS (B_*L_)      // 4096
#define NSPLIT 4
#define SKEYS (S_/NSPLIT) // 512

// ---------------- scratch (no allocations allowed) ----------------
__device__ float g_Q   [ROWS*D_];
__device__ float g_K   [ROWS*D_];
__device__ float g_V   [ROWS*D_];
__device__ float g_O   [ROWS*D_];
__device__ float g_M1  [ROWS*D_];
__device__ float g_Hin [ROWS*2*D_];
__device__ float g_Hre [ROWS*2*D_];
__device__ float g_M2  [ROWS*D_];
__device__ float g_pacc[B_*H_*NSPLIT*HD_*L_];  // [bh][sp][d][q]
__device__ float g_pml [B_*H_*NSPLIT*2*L_];    // [bh][sp][{m,l}][q]

// ---------------- GEMM body: C[M,N] = A[M,K] @ W[N,K]^T ----------------
// 128x64 block tile, 256 threads, 8x4 micro-tile, BK=32.
__device__ __forceinline__ void gemm_body(const float* __restrict__ A,
                                          const float* __restrict__ W,
                                          float* __restrict__ C,
                                          int N, int K, int relu,
                                          int m0, int n0) {
    __shared__ float As[32][132];
    __shared__ float Bs[32][68];
    const int tid = threadIdx.x;
    const int tx = tid & 15, ty = tid >> 4;
    float acc[8][4];
#pragma unroll
    for (int i = 0; i < 8; i++)
#pragma unroll
        for (int j = 0; j < 4; j++) acc[i][j] = 0.f;

    for (int k0 = 0; k0 < K; k0 += 32) {
#pragma unroll
        for (int it = 0; it < 4; it++) {              // A: 128x32 = 1024 float4
            int idx = tid + it * 256;
            int r = idx >> 3, c = idx & 7;
            float4 a = *(const float4*)(A + (size_t)(m0 + r) * K + k0 + 4 * c);
            As[4*c+0][r] = a.x; As[4*c+1][r] = a.y; As[4*c+2][r] = a.z; As[4*c+3][r] = a.w;
        }
#pragma unroll
        for (int it = 0; it < 2; it++) {              // B: 64x32 = 512 float4
            int idx = tid + it * 256;
            int r = idx >> 3, c = idx & 7;
            float4 w = *(const float4*)(W + (size_t)(n0 + r) * K + k0 + 4 * c);
            Bs[4*c+0][r] = w.x; Bs[4*c+1][r] = w.y; Bs[4*c+2][r] = w.z; Bs[4*c+3][r] = w.w;
        }
        __syncthreads();
#pragma unroll
        for (int k = 0; k < 32; k++) {
            float4 a0 = *(const float4*)&As[k][ty * 8];
            float4 a1 = *(const float4*)&As[k][ty * 8 + 4];
            float4 b  = *(const float4*)&Bs[k][tx * 4];
            acc[0][0] += a0.x*b.x; acc[0][1] += a0.x*b.y; acc[0][2] += a0.x*b.z; acc[0][3] += a0.x*b.w;
            acc[1][0] += a0.y*b.x; acc[1][1] += a0.y*b.y; acc[1][2] += a0.y*b.z; acc[1][3] += a0.y*b.w;
            acc[2][0] += a0.z*b.x; acc[2][1] += a0.z*b.y; acc[2][2] += a0.z*b.z; acc[2][3] += a0.z*b.w;
            acc[3][0] += a0.w*b.x; acc[3][1] += a0.w*b.y; acc[3][2] += a0.w*b.z; acc[3][3] += a0.w*b.w;
            acc[4][0] += a1.x*b.x; acc[4][1] += a1.x*b.y; acc[4][2] += a1.x*b.z; acc[4][3] += a1.x*b.w;
            acc[5][0] += a1.y*b.x; acc[5][1] += a1.y*b.y; acc[5][2] += a1.y*b.z; acc[5][3] += a1.y*b.w;
            acc[6][0] += a1.z*b.x; acc[6][1] += a1.z*b.y; acc[6][2] += a1.z*b.z; acc[6][3] += a1.z*b.w;
            acc[7][0] += a1.w*b.x; acc[7][1] += a1.w*b.y; acc[7][2] += a1.w*b.z; acc[7][3] += a1.w*b.w;
        }
        __syncthreads();
    }
#pragma unroll
    for (int i = 0; i < 8; i++) {
        float4 o;
        o.x = acc[i][0]; o.y = acc[i][1]; o.z = acc[i][2]; o.w = acc[i][3];
        if (relu) {
            o.x = fmaxf(o.x, 0.f); o.y = fmaxf(o.y, 0.f);
            o.z = fmaxf(o.z, 0.f); o.w = fmaxf(o.w, 0.f);
        }
        *(float4*)(C + (size_t)(m0 + ty * 8 + i) * N + n0 + tx * 4) = o;
    }
}

__global__ void __launch_bounds__(256) gemm_nt(const float* __restrict__ A,
                                               const float* __restrict__ W,
                                               float* __restrict__ C,
                                               int N, int K, int relu) {
    gemm_body(A, W, C, N, K, relu, blockIdx.y * 128, blockIdx.x * 64);
}

// Q/K/V projections batched over blockIdx.z to fill the chip in one wave.
__global__ void __launch_bounds__(256) gemm_qkv(const float* __restrict__ x,
                                                const float* __restrict__ src,
                                                const float* __restrict__ Wq,
                                                const float* __restrict__ Wk,
                                                const float* __restrict__ Wv,
                                                float* __restrict__ Q,
                                                float* __restrict__ K,
                                                float* __restrict__ V) {
    const float* A; const float* W; float* C;
    if (blockIdx.z == 0)      { A = x;   W = Wq; C = Q; }
    else if (blockIdx.z == 1) { A = src; W = Wk; C = K; }
    else                      { A = src; W = Wv; C = V; }
    gemm_body(A, W, C, D_, D_, 0, blockIdx.y * 128, blockIdx.x * 64);
}

// ---------------- split-KV flash attention ----------------
// grid (L/128, B*H, NSPLIT), 128 threads; thread t owns query row q0+t.
// Writes unnormalized acc + (m,l) partials; attn_combine merges splits.
__global__ void __launch_bounds__(128, 4) attn_split(const float* __restrict__ Q,
                                                     const float* __restrict__ K,
                                                     const float* __restrict__ V,
                                                     const float* __restrict__ AF,
                                                     float* __restrict__ pacc,
                                                     float* __restrict__ pml) {
    __shared__ float4 Ks4[32][8];
    __shared__ float4 Vs4[32][8];
    __shared__ float  AFs[128][33];
    const int bh = blockIdx.y;
    const int b  = bh >> 3;           // H = 8
    const int h  = bh & 7;
    const int sp = blockIdx.z;
    const int q0 = blockIdx.x * 128;
    const int tid = threadIdx.x;
    const float scale = 0.17677669529663687f;  // 1/sqrt(32)

    const float* qptr = Q + ((size_t)(b * L_ + q0 + tid)) * D_ + h * HD_;
    float q[32];
#pragma unroll
    for (int c = 0; c < 8; c++) {
        float4 t = *(const float4*)(qptr + 4 * c);
        q[4*c] = t.x; q[4*c+1] = t.y; q[4*c+2] = t.z; q[4*c+3] = t.w;
    }
    float m = -3.0e38f, l = 0.f;
    float acc[32];
#pragma unroll
    for (int d = 0; d < 32; d++) acc[d] = 0.f;

    const float* afbase = AF + ((size_t)b * L_ + q0) * S_;
    const int s_begin = sp * SKEYS;

    for (int s0 = s_begin; s0 < s_begin + SKEYS; s0 += 32) {
#pragma unroll
        for (int it = 0; it < 2; it++) {
            int idx = tid + it * 128;
            int j = idx >> 3, c = idx & 7;
            Ks4[j][c] = *(const float4*)(K + ((size_t)(b * S_ + s0 + j)) * D_ + h * HD_ + 4 * c);
            Vs4[j][c] = *(const float4*)(V + ((size_t)(b * S_ + s0 + j)) * D_ + h * HD_ + 4 * c);
        }
#pragma unroll
        for (int it = 0; it < 8; it++) {
            int idx = tid + it * 128;
            int r = idx >> 3, c = idx & 7;
            float4 v = *(const float4*)(afbase + (size_t)r * S_ + s0 + 4 * c);
            AFs[r][4*c] = v.x; AFs[r][4*c+1] = v.y; AFs[r][4*c+2] = v.z; AFs[r][4*c+3] = v.w;
        }
        __syncthreads();

        // two 16-key sub-chunks: halves register pressure (sc[16] not sc[32])
#pragma unroll
        for (int half = 0; half < 2; half++) {
            float sc[16];
            float tmax = -3.0e38f;
#pragma unroll
            for (int j = 0; j < 16; j++) {
                int jj = half * 16 + j;
                float s = 0.f;
#pragma unroll
                for (int c = 0; c < 8; c++) {
                    float4 kk = Ks4[jj][c];
                    s += q[4*c] * kk.x + q[4*c+1] * kk.y + q[4*c+2] * kk.z + q[4*c+3] * kk.w;
                }
                s = s * scale * AFs[tid][jj];
                sc[j] = s;
                tmax = fmaxf(tmax, s);
            }
            float m_new = fmaxf(m, tmax);
            float corr = __expf(m - m_new);
            float psum = 0.f;
#pragma unroll
            for (int j = 0; j < 16; j++) { float p = __expf(sc[j] - m_new); sc[j] = p; psum += p; }
            l = l * corr + psum;
            m = m_new;
#pragma unroll
            for (int d = 0; d < 32; d++) acc[d] *= corr;
#pragma unroll
            for (int j = 0; j < 16; j++) {
                int jj = half * 16 + j;
                float p = sc[j];
#pragma unroll
                for (int c = 0; c < 8; c++) {
                    float4 vv = Vs4[jj][c];
                    acc[4*c]   += p * vv.x;
                    acc[4*c+1] += p * vv.y;
                    acc[4*c+2] += p * vv.z;
                    acc[4*c+3] += p * vv.w;
                }
            }
        }
        __syncthreads();
    }
    // coalesced partial writes: [bh][sp][d][q]
    const int qg = q0 + tid;
    float* pa = pacc + ((size_t)(bh * NSPLIT + sp) * HD_) * L_ + qg;
#pragma unroll
    for (int d = 0; d < 32; d++) pa[(size_t)d * L_] = acc[d];
    float* pm = pml + ((size_t)(bh * NSPLIT + sp) * 2) * L_ + qg;
    pm[0]  = m;
    pm[L_] = l;
}

// merge NSPLIT partial online-softmax states per query
__global__ void __launch_bounds__(128) attn_combine(const float* __restrict__ pacc,
                                                    const float* __restrict__ pml,
                                                    float* __restrict__ O) {
    const int bh = blockIdx.y;
    const int b  = bh >> 3;
    const int h  = bh & 7;
    const int q  = blockIdx.x * 128 + threadIdx.x;

    float mv[NSPLIT], lv[NSPLIT];
    float M = -3.0e38f;
#pragma unroll
    for (int sp = 0; sp < NSPLIT; sp++) {
        const float* pm = pml + ((size_t)(bh * NSPLIT + sp) * 2) * L_ + q;
        mv[sp] = pm[0];
        lv[sp] = pm[L_];
        M = fmaxf(M, mv[sp]);
    }
    float w[NSPLIT], Lsum = 0.f;
#pragma unroll
    for (int sp = 0; sp < NSPLIT; sp++) {
        w[sp] = __expf(mv[sp] - M);
        Lsum += lv[sp] * w[sp];
    }
    float inv = 1.f / Lsum;
    float* optr = O + ((size_t)(b * L_ + q)) * D_ + h * HD_;
#pragma unroll
    for (int d = 0; d < 32; d++) {
        float o = 0.f;
#pragma unroll
        for (int sp = 0; sp < NSPLIT; sp++)
            o += w[sp] * pacc[((size_t)(bh * NSPLIT + sp) * HD_ + d) * L_ + q];
        optr[d] = o * inv;
    }
}

// ---------------- LN1 fused with concat materialization ----------------
__global__ void __launch_bounds__(256) ln_concat_kernel(const float* __restrict__ M1,
                                                        const float* __restrict__ x,
                                                        const float* __restrict__ g,
                                                        const float* __restrict__ b,
                                                        float* __restrict__ Hin) {
    int warp = threadIdx.x >> 5, lane = threadIdx.x & 31;
    int row = blockIdx.x * 8 + warp;
    const float* p = M1 + (size_t)row * D_;
    float v[8]; float s = 0.f;
#pragma unroll
    for (int k = 0; k < 8; k++) { v[k] = p[lane + 32 * k]; s += v[k]; }
#pragma unroll
    for (int o = 16; o; o >>= 1) s += __shfl_xor_sync(0xffffffffu, s, o);
    float mean = s * (1.f / 256.f);
    float vs = 0.f;
#pragma unroll
    for (int k = 0; k < 8; k++) { float d = v[k] - mean; vs += d * d; }
#pragma unroll
    for (int o = 16; o; o >>= 1) vs += __shfl_xor_sync(0xffffffffu, vs, o);
    float rstd = rsqrtf(vs * (1.f / 256.f) + 1e-5f);
    float* ho = Hin + (size_t)row * (2 * D_);
    const float* xr = x + (size_t)row * D_;
#pragma unroll
    for (int k = 0; k < 8; k++) {
        int col = lane + 32 * k;
        ho[col]      = xr[col];
        ho[D_ + col] = (v[k] - mean) * rstd * g[col] + b[col];
    }
}

// ---------------- LN2 + residual, writes final output ----------------
__global__ void __launch_bounds__(256) ln_residual_kernel(const float* __restrict__ M2,
                                                          const float* __restrict__ x,
                                                          const float* __restrict__ g,
                                                          const float* __restrict__ b,
                                                          float* __restrict__ out) {
    int warp = threadIdx.x >> 5, lane = threadIdx.x & 31;
    int row = blockIdx.x * 8 + warp;
    const float* p = M2 + (size_t)row * D_;
    float v[8]; float s = 0.f;
#pragma unroll
    for (int k = 0; k < 8; k++) { v[k] = p[lane + 32 * k]; s += v[k]; }
#pragma unroll
    for (int o = 16; o; o >>= 1) s += __shfl_xor_sync(0xffffffffu, s, o);
    float mean = s * (1.f / 256.f);
    float vs = 0.f;
#pragma unroll
    for (int k = 0; k < 8; k++) { float d = v[k] - mean; vs += d * d; }
#pragma unroll
    for (int o = 16; o; o >>= 1) vs += __shfl_xor_sync(0xffffffffu, vs, o);
    float rstd = rsqrtf(vs * (1.f / 256.f) + 1e-5f);
    const float* xr = x + (size_t)row * D_;
    float* orow = out + (size_t)row * D_;
#pragma unroll
    for (int k = 0; k < 8; k++) {
        int col = lane + 32 * k;
        orow[col] = xr[col] + (v[k] - mean) * rstd * g[col] + b[col];
    }
}

// ---------------- launch ----------------
extern "C" void kernel_launch(void* const* d_in, const int* in_sizes, int n_in,
                              void* d_out, int out_size) {
    const float* x   = (const float*)d_in[0];
    const float* src = (const float*)d_in[1];
    const float* af  = (const float*)d_in[2];
    const float* Wq  = (const float*)d_in[3];
    const float* Wk  = (const float*)d_in[4];
    const float* Wv  = (const float*)d_in[5];
    const float* Wm  = (const float*)d_in[6];
    const float* W1  = (const float*)d_in[7];
    const float* W2  = (const float*)d_in[8];
    const float* g1  = (const float*)d_in[9];
    const float* b1  = (const float*)d_in[10];
    const float* g2  = (const float*)d_in[11];
    const float* b2  = (const float*)d_in[12];
    float* out = (float*)d_out;

    float *Qp, *Kp, *Vp, *Op, *M1p, *Hin, *Hre, *M2p, *pacc, *pml;
    cudaGetSymbolAddress((void**)&Qp,   g_Q);
    cudaGetSymbolAddress((void**)&Kp,   g_K);
    cudaGetSymbolAddress((void**)&Vp,   g_V);
    cudaGetSymbolAddress((void**)&Op,   g_O);
    cudaGetSymbolAddress((void**)&M1p,  g_M1);
    cudaGetSymbolAddress((void**)&Hin,  g_Hin);
    cudaGetSymbolAddress((void**)&Hre,  g_Hre);
    cudaGetSymbolAddress((void**)&M2p,  g_M2);
    cudaGetSymbolAddress((void**)&pacc, g_pacc);
    cudaGetSymbolAddress((void**)&pml,  g_pml);

    // Q/K/V projections in ONE launch (384 CTAs fills the chip)
    gemm_qkv<<<dim3(D_ / 64, ROWS / 128, 3), 256>>>(x, src, Wq, Wk, Wv, Qp, Kp, Vp);
    // split-KV flash attention: 1024 CTAs
    attn_split<<<dim3(L_ / 128, B_ * H_, NSPLIT), 128>>>(Qp, Kp, Vp, af, pacc, pml);
    attn_combine<<<dim3(L_ / 128, B_ * H_), 128>>>(pacc, pml, Op);
    // message = O @ Wm^T
    gemm_nt<<<dim3(D_ / 64, ROWS / 128), 256>>>(Op, Wm, M1p, D_, D_, 0);
    // LN1 + concat [x, ln(message)]
    ln_concat_kernel<<<ROWS / 8, 256>>>(M1p, x, g1, b1, Hin);
    // h = relu(Hin @ W1^T)
    gemm_nt<<<dim3(2 * D_ / 64, ROWS / 128), 256>>>(Hin, W1, Hre, 2 * D_, 2 * D_, 1);
    // M2 = h @ W2^T
    gemm_nt<<<dim3(D_ / 64, ROWS / 128), 256>>>(Hre, W2, M2p, D_, 2 * D_, 0);
    // out = x + LN2(M2)
    ln_residual_kernel<<<ROWS / 8, 256>>>(M2p, x, g2, b2, out);
}

// round 5
// speedup vs baseline: 1.4835x; 1.2505x over previous
#include <cuda_runtime.h>
#include <math.h>

#define B_  2
#define L_  2048
#define S_  2048
#define D_  256
#define H_  8
#define HD_ 32
#define ROWS (B_*L_)      // 4096

// ---------------- scratch (no allocations allowed) ----------------
__device__ float g_Q   [ROWS*D_];
__device__ float g_K   [ROWS*D_];
__device__ float g_V   [ROWS*D_];
__device__ float g_O   [ROWS*D_];
__device__ float g_M1  [ROWS*D_];
__device__ float g_Hin [ROWS*2*D_];
__device__ float g_Hre [ROWS*2*D_];
__device__ float g_M2  [ROWS*D_];

// ---------------- tf32 helpers ----------------
__device__ __forceinline__ unsigned f2tf(float x) {
    unsigned u;
    asm("cvt.rna.tf32.f32 %0, %1;" : "=r"(u) : "f"(x));
    return u;
}
__device__ __forceinline__ float f2tf_f(float x) { return __uint_as_float(f2tf(x)); }

#define MMA_TF32(d, a0, a1, a2, a3, b0, b1)                                    \
    asm volatile("mma.sync.aligned.m16n8k8.row.col.f32.tf32.tf32.f32 "         \
                 "{%0,%1,%2,%3},{%4,%5,%6,%7},{%8,%9},{%0,%1,%2,%3};"          \
                 : "+f"(d[0]), "+f"(d[1]), "+f"(d[2]), "+f"(d[3])              \
                 : "r"(a0), "r"(a1), "r"(a2), "r"(a3), "r"(b0), "r"(b1))

// ---------------- GEMM body: C[M,N] = A[M,K] @ W[N,K]^T (SIMT, proven) -------
__device__ __forceinline__ void gemm_body(const float* __restrict__ A,
                                          const float* __restrict__ W,
                                          float* __restrict__ C,
                                          int N, int K, int relu,
                                          int m0, int n0) {
    __shared__ float As[32][132];
    __shared__ float Bs[32][68];
    const int tid = threadIdx.x;
    const int tx = tid & 15, ty = tid >> 4;
    float acc[8][4];
#pragma unroll
    for (int i = 0; i < 8; i++)
#pragma unroll
        for (int j = 0; j < 4; j++) acc[i][j] = 0.f;

    for (int k0 = 0; k0 < K; k0 += 32) {
#pragma unroll
        for (int it = 0; it < 4; it++) {
            int idx = tid + it * 256;
            int r = idx >> 3, c = idx & 7;
            float4 a = *(const float4*)(A + (size_t)(m0 + r) * K + k0 + 4 * c);
            As[4*c+0][r] = a.x; As[4*c+1][r] = a.y; As[4*c+2][r] = a.z; As[4*c+3][r] = a.w;
        }
#pragma unroll
        for (int it = 0; it < 2; it++) {
            int idx = tid + it * 256;
            int r = idx >> 3, c = idx & 7;
            float4 w = *(const float4*)(W + (size_t)(n0 + r) * K + k0 + 4 * c);
            Bs[4*c+0][r] = w.x; Bs[4*c+1][r] = w.y; Bs[4*c+2][r] = w.z; Bs[4*c+3][r] = w.w;
        }
        __syncthreads();
#pragma unroll
        for (int k = 0; k < 32; k++) {
            float4 a0 = *(const float4*)&As[k][ty * 8];
            float4 a1 = *(const float4*)&As[k][ty * 8 + 4];
            float4 b  = *(const float4*)&Bs[k][tx * 4];
            acc[0][0] += a0.x*b.x; acc[0][1] += a0.x*b.y; acc[0][2] += a0.x*b.z; acc[0][3] += a0.x*b.w;
            acc[1][0] += a0.y*b.x; acc[1][1] += a0.y*b.y; acc[1][2] += a0.y*b.z; acc[1][3] += a0.y*b.w;
            acc[2][0] += a0.z*b.x; acc[2][1] += a0.z*b.y; acc[2][2] += a0.z*b.z; acc[2][3] += a0.z*b.w;
            acc[3][0] += a0.w*b.x; acc[3][1] += a0.w*b.y; acc[3][2] += a0.w*b.z; acc[3][3] += a0.w*b.w;
            acc[4][0] += a1.x*b.x; acc[4][1] += a1.x*b.y; acc[4][2] += a1.x*b.z; acc[4][3] += a1.x*b.w;
            acc[5][0] += a1.y*b.x; acc[5][1] += a1.y*b.y; acc[5][2] += a1.y*b.z; acc[5][3] += a1.y*b.w;
            acc[6][0] += a1.z*b.x; acc[6][1] += a1.z*b.y; acc[6][2] += a1.z*b.z; acc[6][3] += a1.z*b.w;
            acc[7][0] += a1.w*b.x; acc[7][1] += a1.w*b.y; acc[7][2] += a1.w*b.z; acc[7][3] += a1.w*b.w;
        }
        __syncthreads();
    }
#pragma unroll
    for (int i = 0; i < 8; i++) {
        float4 o;
        o.x = acc[i][0]; o.y = acc[i][1]; o.z = acc[i][2]; o.w = acc[i][3];
        if (relu) {
            o.x = fmaxf(o.x, 0.f); o.y = fmaxf(o.y, 0.f);
            o.z = fmaxf(o.z, 0.f); o.w = fmaxf(o.w, 0.f);
        }
        *(float4*)(C + (size_t)(m0 + ty * 8 + i) * N + n0 + tx * 4) = o;
    }
}

__global__ void __launch_bounds__(256) gemm_nt(const float* __restrict__ A,
                                               const float* __restrict__ W,
                                               float* __restrict__ C,
                                               int N, int K, int relu) {
    gemm_body(A, W, C, N, K, relu, blockIdx.y * 128, blockIdx.x * 64);
}

__global__ void __launch_bounds__(256) gemm_qkv(const float* __restrict__ x,
                                                const float* __restrict__ src,
                                                const float* __restrict__ Wq,
                                                const float* __restrict__ Wk,
                                                const float* __restrict__ Wv,
                                                float* __restrict__ Q,
                                                float* __restrict__ K,
                                                float* __restrict__ V) {
    const float* A; const float* W; float* C;
    if (blockIdx.z == 0)      { A = x;   W = Wq; C = Q; }
    else if (blockIdx.z == 1) { A = src; W = Wk; C = K; }
    else                      { A = src; W = Wv; C = V; }
    gemm_body(A, W, C, D_, D_, 0, blockIdx.y * 128, blockIdx.x * 64);
}

// ---------------- tensor-core flash attention, all heads fused ---------------
// CTA = 16 queries x ALL 8 heads. 8 warps; warp w = head w (16q x 32 head-dim).
// s-tile = 32 keys. AF tile is loaded ONCE and shared by all heads.
// tf32 mma m16n8k8: QK^T (k=headdim 32) and P.V (k=s-tile 32).
// smem layout (floats):
//   Ks [32][268], Vs [32][268]   (tf32-rounded, padded: stride 268 -> no QK B-frag bank conflicts)
//   AFs[16][36]
//   Ps [8 warps][16][36]         (tf32-rounded probabilities, warp-private)
#define KV_STRIDE 268
#define AF_STRIDE 36
#define SMEM_ATTN_FLOATS (2*32*KV_STRIDE + 16*AF_STRIDE + 8*16*AF_STRIDE)

__global__ void __launch_bounds__(256, 2) attn_tc(const float* __restrict__ Q,
                                                  const float* __restrict__ K,
                                                  const float* __restrict__ V,
                                                  const float* __restrict__ AF,
                                                  float* __restrict__ O) {
    extern __shared__ float sm[];
    float* Ks  = sm;
    float* Vs  = sm + 32 * KV_STRIDE;
    float* AFs = Vs + 32 * KV_STRIDE;
    float* Ps  = AFs + 16 * AF_STRIDE;

    const int b   = blockIdx.y;
    const int q0  = blockIdx.x * 16;
    const int tid = threadIdx.x;
    const int w   = tid >> 5;        // warp == head
    const int lane = tid & 31;
    const int g  = lane >> 2;        // groupID (0..7)
    const int tg = lane & 3;         // threadID_in_group (0..3)
    const int h  = w;
    const float scale = 0.17677669529663687f;  // 1/sqrt(32)

    // --- Q fragments: A[16 x 32], 4 k-steps of m16k8 ---
    unsigned qa[4][4];
    {
        const float* qb = Q + ((size_t)(b * L_ + q0)) * D_ + h * HD_;
#pragma unroll
        for (int kk = 0; kk < 4; kk++) {
            qa[kk][0] = f2tf(qb[(size_t)g       * D_ + kk * 8 + tg]);
            qa[kk][1] = f2tf(qb[(size_t)(g + 8) * D_ + kk * 8 + tg]);
            qa[kk][2] = f2tf(qb[(size_t)g       * D_ + kk * 8 + tg + 4]);
            qa[kk][3] = f2tf(qb[(size_t)(g + 8) * D_ + kk * 8 + tg + 4]);
        }
    }

    float ma = -3.0e38f, mb = -3.0e38f, la = 0.f, lb = 0.f;
    float oacc[4][4];
#pragma unroll
    for (int nt = 0; nt < 4; nt++)
#pragma unroll
        for (int i = 0; i < 4; i++) oacc[nt][i] = 0.f;

    float* Pw = Ps + w * (16 * AF_STRIDE);

    for (int s0 = 0; s0 < S_; s0 += 32) {
        // --- stage K, V (tf32-rounded) and AF tile ---
#pragma unroll
        for (int i = 0; i < 8; i++) {
            int idx = tid + i * 256;         // 0..2047
            int r = idx >> 6, c4 = (idx & 63) * 4;
            float4 kv = *(const float4*)(K + ((size_t)(b * S_ + s0 + r)) * D_ + c4);
            kv.x = f2tf_f(kv.x); kv.y = f2tf_f(kv.y); kv.z = f2tf_f(kv.z); kv.w = f2tf_f(kv.w);
            *(float4*)(Ks + r * KV_STRIDE + c4) = kv;
            float4 vv = *(const float4*)(V + ((size_t)(b * S_ + s0 + r)) * D_ + c4);
            vv.x = f2tf_f(vv.x); vv.y = f2tf_f(vv.y); vv.z = f2tf_f(vv.z); vv.w = f2tf_f(vv.w);
            *(float4*)(Vs + r * KV_STRIDE + c4) = vv;
        }
        if (tid < 128) {
            int r = tid >> 3, c4 = (tid & 7) * 4;
            *(float4*)(AFs + r * AF_STRIDE + c4) =
                *(const float4*)(AF + ((size_t)(b * L_ + q0 + r)) * S_ + s0 + c4);
        }
        __syncthreads();

        // --- S = Q K^T : [16 x 32] ---
        float sc[4][4];
        float mxa = -3.0e38f, mxb = -3.0e38f;
#pragma unroll
        for (int nt = 0; nt < 4; nt++) {
            sc[nt][0] = 0.f; sc[nt][1] = 0.f; sc[nt][2] = 0.f; sc[nt][3] = 0.f;
#pragma unroll
            for (int kk = 0; kk < 4; kk++) {
                unsigned b0 = __float_as_uint(Ks[(nt * 8 + g) * KV_STRIDE + h * HD_ + kk * 8 + tg]);
                unsigned b1 = __float_as_uint(Ks[(nt * 8 + g) * KV_STRIDE + h * HD_ + kk * 8 + tg + 4]);
                MMA_TF32(sc[nt], qa[kk][0], qa[kk][1], qa[kk][2], qa[kk][3], b0, b1);
            }
            // apply scale * AF in place (C layout: rows g/g+8, cols nt*8+2tg{,+1})
            sc[nt][0] *= scale * AFs[g * AF_STRIDE + nt * 8 + 2 * tg];
            sc[nt][1] *= scale * AFs[g * AF_STRIDE + nt * 8 + 2 * tg + 1];
            sc[nt][2] *= scale * AFs[(g + 8) * AF_STRIDE + nt * 8 + 2 * tg];
            sc[nt][3] *= scale * AFs[(g + 8) * AF_STRIDE + nt * 8 + 2 * tg + 1];
            mxa = fmaxf(mxa, fmaxf(sc[nt][0], sc[nt][1]));
            mxb = fmaxf(mxb, fmaxf(sc[nt][2], sc[nt][3]));
        }
        // row max across the 4 threads of the group
        mxa = fmaxf(mxa, __shfl_xor_sync(0xffffffffu, mxa, 1));
        mxa = fmaxf(mxa, __shfl_xor_sync(0xffffffffu, mxa, 2));
        mxb = fmaxf(mxb, __shfl_xor_sync(0xffffffffu, mxb, 1));
        mxb = fmaxf(mxb, __shfl_xor_sync(0xffffffffu, mxb, 2));

        float mna = fmaxf(ma, mxa), mnb = fmaxf(mb, mxb);
        float ca = __expf(ma - mna), cb = __expf(mb - mnb);
        ma = mna; mb = mnb;

        float pa = 0.f, pb = 0.f;
#pragma unroll
        for (int nt = 0; nt < 4; nt++) {
            float p0 = f2tf_f(__expf(sc[nt][0] - mna));
            float p1 = f2tf_f(__expf(sc[nt][1] - mna));
            float p2 = f2tf_f(__expf(sc[nt][2] - mnb));
            float p3 = f2tf_f(__expf(sc[nt][3] - mnb));
            pa += p0 + p1; pb += p2 + p3;
            Pw[g * AF_STRIDE + nt * 8 + 2 * tg]           = p0;
            Pw[g * AF_STRIDE + nt * 8 + 2 * tg + 1]       = p1;
            Pw[(g + 8) * AF_STRIDE + nt * 8 + 2 * tg]     = p2;
            Pw[(g + 8) * AF_STRIDE + nt * 8 + 2 * tg + 1] = p3;
        }
        la = la * ca + pa;
        lb = lb * cb + pb;
#pragma unroll
        for (int nt = 0; nt < 4; nt++) {
            oacc[nt][0] *= ca; oacc[nt][1] *= ca;
            oacc[nt][2] *= cb; oacc[nt][3] *= cb;
        }
        __syncwarp();

        // --- O += P V : [16 x 32], k = s-tile (32) ---
#pragma unroll
        for (int kk = 0; kk < 4; kk++) {
            unsigned a0 = __float_as_uint(Pw[g * AF_STRIDE + kk * 8 + tg]);
            unsigned a1 = __float_as_uint(Pw[(g + 8) * AF_STRIDE + kk * 8 + tg]);
            unsigned a2 = __float_as_uint(Pw[g * AF_STRIDE + kk * 8 + tg + 4]);
            unsigned a3 = __float_as_uint(Pw[(g + 8) * AF_STRIDE + kk * 8 + tg + 4]);
#pragma unroll
            for (int nt = 0; nt < 4; nt++) {
                unsigned b0 = __float_as_uint(Vs[(kk * 8 + tg)     * KV_STRIDE + h * HD_ + nt * 8 + g]);
                unsigned b1 = __float_as_uint(Vs[(kk * 8 + tg + 4) * KV_STRIDE + h * HD_ + nt * 8 + g]);
                MMA_TF32(oacc[nt], a0, a1, a2, a3, b0, b1);
            }
        }
        __syncthreads();
    }

    // reduce l across the group, normalize, write out
    la += __shfl_xor_sync(0xffffffffu, la, 1);
    la += __shfl_xor_sync(0xffffffffu, la, 2);
    lb += __shfl_xor_sync(0xffffffffu, lb, 1);
    lb += __shfl_xor_sync(0xffffffffu, lb, 2);
    float inva = 1.f / la, invb = 1.f / lb;

    float* orow_a = O + ((size_t)(b * L_ + q0 + g))     * D_ + h * HD_;
    float* orow_b = O + ((size_t)(b * L_ + q0 + g + 8)) * D_ + h * HD_;
#pragma unroll
    for (int nt = 0; nt < 4; nt++) {
        orow_a[nt * 8 + 2 * tg]     = oacc[nt][0] * inva;
        orow_a[nt * 8 + 2 * tg + 1] = oacc[nt][1] * inva;
        orow_b[nt * 8 + 2 * tg]     = oacc[nt][2] * invb;
        orow_b[nt * 8 + 2 * tg + 1] = oacc[nt][3] * invb;
    }
}

// ---------------- LN1 fused with concat materialization ----------------
__global__ void __launch_bounds__(256) ln_concat_kernel(const float* __restrict__ M1,
                                                        const float* __restrict__ x,
                                                        const float* __restrict__ g,
                                                        const float* __restrict__ b,
                                                        float* __restrict__ Hin) {
    int warp = threadIdx.x >> 5, lane = threadIdx.x & 31;
    int row = blockIdx.x * 8 + warp;
    const float* p = M1 + (size_t)row * D_;
    float v[8]; float s = 0.f;
#pragma unroll
    for (int k = 0; k < 8; k++) { v[k] = p[lane + 32 * k]; s += v[k]; }
#pragma unroll
    for (int o = 16; o; o >>= 1) s += __shfl_xor_sync(0xffffffffu, s, o);
    float mean = s * (1.f / 256.f);
    float vs = 0.f;
#pragma unroll
    for (int k = 0; k < 8; k++) { float d = v[k] - mean; vs += d * d; }
#pragma unroll
    for (int o = 16; o; o >>= 1) vs += __shfl_xor_sync(0xffffffffu, vs, o);
    float rstd = rsqrtf(vs * (1.f / 256.f) + 1e-5f);
    float* ho = Hin + (size_t)row * (2 * D_);
    const float* xr = x + (size_t)row * D_;
#pragma unroll
    for (int k = 0; k < 8; k++) {
        int col = lane + 32 * k;
        ho[col]      = xr[col];
        ho[D_ + col] = (v[k] - mean) * rstd * g[col] + b[col];
    }
}

// ---------------- LN2 + residual, writes final output ----------------
__global__ void __launch_bounds__(256) ln_residual_kernel(const float* __restrict__ M2,
                                                          const float* __restrict__ x,
                                                          const float* __restrict__ g,
                                                          const float* __restrict__ b,
                                                          float* __restrict__ out) {
    int warp = threadIdx.x >> 5, lane = threadIdx.x & 31;
    int row = blockIdx.x * 8 + warp;
    const float* p = M2 + (size_t)row * D_;
    float v[8]; float s = 0.f;
#pragma unroll
    for (int k = 0; k < 8; k++) { v[k] = p[lane + 32 * k]; s += v[k]; }
#pragma unroll
    for (int o = 16; o; o >>= 1) s += __shfl_xor_sync(0xffffffffu, s, o);
    float mean = s * (1.f / 256.f);
    float vs = 0.f;
#pragma unroll
    for (int k = 0; k < 8; k++) { float d = v[k] - mean; vs += d * d; }
#pragma unroll
    for (int o = 16; o; o >>= 1) vs += __shfl_xor_sync(0xffffffffu, vs, o);
    float rstd = rsqrtf(vs * (1.f / 256.f) + 1e-5f);
    const float* xr = x + (size_t)row * D_;
    float* orow = out + (size_t)row * D_;
#pragma unroll
    for (int k = 0; k < 8; k++) {
        int col = lane + 32 * k;
        orow[col] = xr[col] + (v[k] - mean) * rstd * g[col] + b[col];
    }
}

// ---------------- launch ----------------
extern "C" void kernel_launch(void* const* d_in, const int* in_sizes, int n_in,
                              void* d_out, int out_size) {
    const float* x   = (const float*)d_in[0];
    const float* src = (const float*)d_in[1];
    const float* af  = (const float*)d_in[2];
    const float* Wq  = (const float*)d_in[3];
    const float* Wk  = (const float*)d_in[4];
    const float* Wv  = (const float*)d_in[5];
    const float* Wm  = (const float*)d_in[6];
    const float* W1  = (const float*)d_in[7];
    const float* W2  = (const float*)d_in[8];
    const float* g1  = (const float*)d_in[9];
    const float* b1  = (const float*)d_in[10];
    const float* g2  = (const float*)d_in[11];
    const float* b2  = (const float*)d_in[12];
    float* out = (float*)d_out;

    float *Qp, *Kp, *Vp, *Op, *M1p, *Hin, *Hre, *M2p;
    cudaGetSymbolAddress((void**)&Qp,  g_Q);
    cudaGetSymbolAddress((void**)&Kp,  g_K);
    cudaGetSymbolAddress((void**)&Vp,  g_V);
    cudaGetSymbolAddress((void**)&Op,  g_O);
    cudaGetSymbolAddress((void**)&M1p, g_M1);
    cudaGetSymbolAddress((void**)&Hin, g_Hin);
    cudaGetSymbolAddress((void**)&Hre, g_Hre);
    cudaGetSymbolAddress((void**)&M2p, g_M2);

    const int attn_smem = SMEM_ATTN_FLOATS * (int)sizeof(float);  // ~89 KB
    cudaFuncSetAttribute(attn_tc, cudaFuncAttributeMaxDynamicSharedMemorySize, attn_smem);

    // Q/K/V projections in one launch (384 CTAs)
    gemm_qkv<<<dim3(D_ / 64, ROWS / 128, 3), 256>>>(x, src, Wq, Wk, Wv, Qp, Kp, Vp);
    // tensor-core flash attention, all heads per CTA (256 CTAs, 2/SM)
    attn_tc<<<dim3(L_ / 16, B_), 256, attn_smem>>>(Qp, Kp, Vp, af, Op);
    // message = O @ Wm^T
    gemm_nt<<<dim3(D_ / 64, ROWS / 128), 256>>>(Op, Wm, M1p, D_, D_, 0);
    // LN1 + concat [x, ln(message)]
    ln_concat_kernel<<<ROWS / 8, 256>>>(M1p, x, g1, b1, Hin);
    // h = relu(Hin @ W1^T)
    gemm_nt<<<dim3(2 * D_ / 64, ROWS / 128), 256>>>(Hin, W1, Hre, 2 * D_, 2 * D_, 1);
    // M2 = h @ W2^T
    gemm_nt<<<dim3(D_ / 64, ROWS / 128), 256>>>(Hre, W2, M2p, D_, 2 * D_, 0);
    // out = x + LN2(M2)
    ln_residual_kernel<<<ROWS / 8, 256>>>(M2p, x, g2, b2, out);
}

// round 8
// speedup vs baseline: 1.8957x; 1.2779x over previous
#include <cuda_runtime.h>
#include <math.h>

#define B_  2
#define L_  2048
#define S_  2048
#define D_  256
#define H_  8
#define HD_ 32
#define ROWS (B_*L_)      // 4096

// ---------------- scratch (no allocations allowed) ----------------
__device__ float g_Q   [ROWS*D_];
__device__ float g_K   [ROWS*D_];
__device__ float g_V   [ROWS*D_];
__device__ float g_O   [ROWS*D_];
__device__ float g_M1  [ROWS*D_];
__device__ float g_Hin [ROWS*2*D_];
__device__ float g_Hre [ROWS*2*D_];
__device__ float g_M2  [ROWS*D_];

// ---------------- tf32 helpers ----------------
__device__ __forceinline__ unsigned f2tf(float x) {
    unsigned u;
    asm("cvt.rna.tf32.f32 %0, %1;" : "=r"(u) : "f"(x));
    return u;
}
__device__ __forceinline__ float f2tf_f(float x) { return __uint_as_float(f2tf(x)); }

#define MMA_TF32(d, a0, a1, a2, a3, b0, b1)                                    \
    asm volatile("mma.sync.aligned.m16n8k8.row.col.f32.tf32.tf32.f32 "         \
                 "{%0,%1,%2,%3},{%4,%5,%6,%7},{%8,%9},{%0,%1,%2,%3};"          \
                 : "+f"(d[0]), "+f"(d[1]), "+f"(d[2]), "+f"(d[3])              \
                 : "r"(a0), "r"(a1), "r"(a2), "r"(a3), "r"(b0), "r"(b1))

// ============== tf32 tensor-core GEMM: C[M,N] = A[M,K] @ W[N,K]^T ============
// Block tile 128 x BN, 256 threads (8 warps). Warp tile 32 x (BN/2).
// Smem tiles stored row-major [row][k] with stride 36 (4 banks skew):
//   fragment read bank = (4*row + k) % 32 -> all 32 lanes distinct, conflict-free.
// Staging: one float4 global load -> one STS.128, coalesced both sides.
template<int BN>
__device__ __forceinline__ void gemm_tc_body(const float* __restrict__ A,
                                             const float* __restrict__ W,
                                             float* __restrict__ C,
                                             int N, int K, int relu,
                                             int m0, int n0) {
    __shared__ float As[128][36];
    __shared__ float Bs[BN][36];
    constexpr int NT = BN / 16;          // n8 tiles per warp
    const int tid  = threadIdx.x;
    const int w    = tid >> 5, lane = tid & 31;
    const int g    = lane >> 2, tg = lane & 3;
    const int mw   = (w >> 1) * 32;      // warp m offset
    const int nw   = (w & 1) * (BN / 2); // warp n offset

    float acc[2][NT][4];
#pragma unroll
    for (int mi = 0; mi < 2; mi++)
#pragma unroll
        for (int nt = 0; nt < NT; nt++)
#pragma unroll
            for (int i = 0; i < 4; i++) acc[mi][nt][i] = 0.f;

    for (int k0 = 0; k0 < K; k0 += 32) {
        // stage A: 128x32, 1024 float4 / 256 threads = 4
#pragma unroll
        for (int it = 0; it < 4; it++) {
            int idx = tid + it * 256;
            int r = idx >> 3, c = (idx & 7) * 4;
            float4 a = *(const float4*)(A + (size_t)(m0 + r) * K + k0 + c);
            a.x = f2tf_f(a.x); a.y = f2tf_f(a.y); a.z = f2tf_f(a.z); a.w = f2tf_f(a.w);
            *(float4*)(&As[r][c]) = a;
        }
        // stage B: BNx32
#pragma unroll
        for (int it = 0; it < BN / 32; it++) {
            int idx = tid + it * 256;
            int r = idx >> 3, c = (idx & 7) * 4;
            float4 b = *(const float4*)(W + (size_t)(n0 + r) * K + k0 + c);
            b.x = f2tf_f(b.x); b.y = f2tf_f(b.y); b.z = f2tf_f(b.z); b.w = f2tf_f(b.w);
            *(float4*)(&Bs[r][c]) = b;
        }
        __syncthreads();

#pragma unroll
        for (int kk = 0; kk < 4; kk++) {
            unsigned af[2][4];
#pragma unroll
            for (int mi = 0; mi < 2; mi++) {
                int mr = mw + mi * 16;
                af[mi][0] = __float_as_uint(As[mr + g    ][kk * 8 + tg]);
                af[mi][1] = __float_as_uint(As[mr + g + 8][kk * 8 + tg]);
                af[mi][2] = __float_as_uint(As[mr + g    ][kk * 8 + tg + 4]);
                af[mi][3] = __float_as_uint(As[mr + g + 8][kk * 8 + tg + 4]);
            }
            unsigned bf[NT][2];
#pragma unroll
            for (int nt = 0; nt < NT; nt++) {
                bf[nt][0] = __float_as_uint(Bs[nw + nt * 8 + g][kk * 8 + tg]);
                bf[nt][1] = __float_as_uint(Bs[nw + nt * 8 + g][kk * 8 + tg + 4]);
            }
#pragma unroll
            for (int mi = 0; mi < 2; mi++)
#pragma unroll
                for (int nt = 0; nt < NT; nt++)
                    MMA_TF32(acc[mi][nt], af[mi][0], af[mi][1], af[mi][2], af[mi][3],
                             bf[nt][0], bf[nt][1]);
        }
        __syncthreads();
    }

    // epilogue: c0,c1 -> row g; c2,c3 -> row g+8; cols 2tg, 2tg+1
#pragma unroll
    for (int mi = 0; mi < 2; mi++) {
        int row0 = m0 + mw + mi * 16 + g;
#pragma unroll
        for (int nt = 0; nt < NT; nt++) {
            int col = n0 + nw + nt * 8 + 2 * tg;
            float2 v0 = make_float2(acc[mi][nt][0], acc[mi][nt][1]);
            float2 v1 = make_float2(acc[mi][nt][2], acc[mi][nt][3]);
            if (relu) {
                v0.x = fmaxf(v0.x, 0.f); v0.y = fmaxf(v0.y, 0.f);
                v1.x = fmaxf(v1.x, 0.f); v1.y = fmaxf(v1.y, 0.f);
            }
            *(float2*)(C + (size_t)row0 * N + col)       = v0;
            *(float2*)(C + (size_t)(row0 + 8) * N + col) = v1;
        }
    }
}

template<int BN>
__global__ void __launch_bounds__(256) gemm_tc(const float* __restrict__ A,
                                               const float* __restrict__ W,
                                               float* __restrict__ C,
                                               int N, int K, int relu) {
    gemm_tc_body<BN>(A, W, C, N, K, relu, blockIdx.y * 128, blockIdx.x * BN);
}

// Q/K/V projections batched over blockIdx.z (384 CTAs, one wave)
__global__ void __launch_bounds__(256) gemm_qkv_tc(const float* __restrict__ x,
                                                   const float* __restrict__ src,
                                                   const float* __restrict__ Wq,
                                                   const float* __restrict__ Wk,
                                                   const float* __restrict__ Wv,
                                                   float* __restrict__ Q,
                                                   float* __restrict__ K,
                                                   float* __restrict__ V) {
    const float* A; const float* W; float* C;
    if (blockIdx.z == 0)      { A = x;   W = Wq; C = Q; }
    else if (blockIdx.z == 1) { A = src; W = Wk; C = K; }
    else                      { A = src; W = Wv; C = V; }
    gemm_tc_body<64>(A, W, C, D_, D_, 0, blockIdx.y * 128, blockIdx.x * 64);
}

// ---------------- tensor-core flash attention, all heads fused ---------------
// (unchanged — proven in round 5)
#define KV_STRIDE 268
#define AF_STRIDE 36
#define SMEM_ATTN_FLOATS (2*32*KV_STRIDE + 16*AF_STRIDE + 8*16*AF_STRIDE)

__global__ void __launch_bounds__(256, 2) attn_tc(const float* __restrict__ Q,
                                                  const float* __restrict__ K,
                                                  const float* __restrict__ V,
                                                  const float* __restrict__ AF,
                                                  float* __restrict__ O) {
    extern __shared__ float sm[];
    float* Ks  = sm;
    float* Vs  = sm + 32 * KV_STRIDE;
    float* AFs = Vs + 32 * KV_STRIDE;
    float* Ps  = AFs + 16 * AF_STRIDE;

    const int b   = blockIdx.y;
    const int q0  = blockIdx.x * 16;
    const int tid = threadIdx.x;
    const int w   = tid >> 5;
    const int lane = tid & 31;
    const int g  = lane >> 2;
    const int tg = lane & 3;
    const int h  = w;
    const float scale = 0.17677669529663687f;

    unsigned qa[4][4];
    {
        const float* qb = Q + ((size_t)(b * L_ + q0)) * D_ + h * HD_;
#pragma unroll
        for (int kk = 0; kk < 4; kk++) {
            qa[kk][0] = f2tf(qb[(size_t)g       * D_ + kk * 8 + tg]);
            qa[kk][1] = f2tf(qb[(size_t)(g + 8) * D_ + kk * 8 + tg]);
            qa[kk][2] = f2tf(qb[(size_t)g       * D_ + kk * 8 + tg + 4]);
            qa[kk][3] = f2tf(qb[(size_t)(g + 8) * D_ + kk * 8 + tg + 4]);
        }
    }

    float ma = -3.0e38f, mb = -3.0e38f, la = 0.f, lb = 0.f;
    float oacc[4][4];
#pragma unroll
    for (int nt = 0; nt < 4; nt++)
#pragma unroll
        for (int i = 0; i < 4; i++) oacc[nt][i] = 0.f;

    float* Pw = Ps + w * (16 * AF_STRIDE);

    for (int s0 = 0; s0 < S_; s0 += 32) {
#pragma unroll
        for (int i = 0; i < 8; i++) {
            int idx = tid + i * 256;
            int r = idx >> 6, c4 = (idx & 63) * 4;
            float4 kv = *(const float4*)(K + ((size_t)(b * S_ + s0 + r)) * D_ + c4);
            kv.x = f2tf_f(kv.x); kv.y = f2tf_f(kv.y); kv.z = f2tf_f(kv.z); kv.w = f2tf_f(kv.w);
            *(float4*)(Ks + r * KV_STRIDE + c4) = kv;
            float4 vv = *(const float4*)(V + ((size_t)(b * S_ + s0 + r)) * D_ + c4);
            vv.x = f2tf_f(vv.x); vv.y = f2tf_f(vv.y); vv.z = f2tf_f(vv.z); vv.w = f2tf_f(vv.w);
            *(float4*)(Vs + r * KV_STRIDE + c4) = vv;
        }
        if (tid < 128) {
            int r = tid >> 3, c4 = (tid & 7) * 4;
            *(float4*)(AFs + r * AF_STRIDE + c4) =
                *(const float4*)(AF + ((size_t)(b * L_ + q0 + r)) * S_ + s0 + c4);
        }
        __syncthreads();

        float sc[4][4];
        float mxa = -3.0e38f, mxb = -3.0e38f;
#pragma unroll
        for (int nt = 0; nt < 4; nt++) {
            sc[nt][0] = 0.f; sc[nt][1] = 0.f; sc[nt][2] = 0.f; sc[nt][3] = 0.f;
#pragma unroll
            for (int kk = 0; kk < 4; kk++) {
                unsigned b0 = __float_as_uint(Ks[(nt * 8 + g) * KV_STRIDE + h * HD_ + kk * 8 + tg]);
                unsigned b1 = __float_as_uint(Ks[(nt * 8 + g) * KV_STRIDE + h * HD_ + kk * 8 + tg + 4]);
                MMA_TF32(sc[nt], qa[kk][0], qa[kk][1], qa[kk][2], qa[kk][3], b0, b1);
            }
            sc[nt][0] *= scale * AFs[g * AF_STRIDE + nt * 8 + 2 * tg];
            sc[nt][1] *= scale * AFs[g * AF_STRIDE + nt * 8 + 2 * tg + 1];
            sc[nt][2] *= scale * AFs[(g + 8) * AF_STRIDE + nt * 8 + 2 * tg];
            sc[nt][3] *= scale * AFs[(g + 8) * AF_STRIDE + nt * 8 + 2 * tg + 1];
            mxa = fmaxf(mxa, fmaxf(sc[nt][0], sc[nt][1]));
            mxb = fmaxf(mxb, fmaxf(sc[nt][2], sc[nt][3]));
        }
        mxa = fmaxf(mxa, __shfl_xor_sync(0xffffffffu, mxa, 1));
        mxa = fmaxf(mxa, __shfl_xor_sync(0xffffffffu, mxa, 2));
        mxb = fmaxf(mxb, __shfl_xor_sync(0xffffffffu, mxb, 1));
        mxb = fmaxf(mxb, __shfl_xor_sync(0xffffffffu, mxb, 2));

        float mna = fmaxf(ma, mxa), mnb = fmaxf(mb, mxb);
        float ca = __expf(ma - mna), cb = __expf(mb - mnb);
        ma = mna; mb = mnb;

        float pa = 0.f, pb = 0.f;
#pragma unroll
        for (int nt = 0; nt < 4; nt++) {
            float p0 = f2tf_f(__expf(sc[nt][0] - mna));
            float p1 = f2tf_f(__expf(sc[nt][1] - mna));
            float p2 = f2tf_f(__expf(sc[nt][2] - mnb));
            float p3 = f2tf_f(__expf(sc[nt][3] - mnb));
            pa += p0 + p1; pb += p2 + p3;
            Pw[g * AF_STRIDE + nt * 8 + 2 * tg]           = p0;
            Pw[g * AF_STRIDE + nt * 8 + 2 * tg + 1]       = p1;
            Pw[(g + 8) * AF_STRIDE + nt * 8 + 2 * tg]     = p2;
            Pw[(g + 8) * AF_STRIDE + nt * 8 + 2 * tg + 1] = p3;
        }
        la = la * ca + pa;
        lb = lb * cb + pb;
#pragma unroll
        for (int nt = 0; nt < 4; nt++) {
            oacc[nt][0] *= ca; oacc[nt][1] *= ca;
            oacc[nt][2] *= cb; oacc[nt][3] *= cb;
        }
        __syncwarp();

#pragma unroll
        for (int kk = 0; kk < 4; kk++) {
            unsigned a0 = __float_as_uint(Pw[g * AF_STRIDE + kk * 8 + tg]);
            unsigned a1 = __float_as_uint(Pw[(g + 8) * AF_STRIDE + kk * 8 + tg]);
            unsigned a2 = __float_as_uint(Pw[g * AF_STRIDE + kk * 8 + tg + 4]);
            unsigned a3 = __float_as_uint(Pw[(g + 8) * AF_STRIDE + kk * 8 + tg + 4]);
#pragma unroll
            for (int nt = 0; nt < 4; nt++) {
                unsigned b0 = __float_as_uint(Vs[(kk * 8 + tg)     * KV_STRIDE + h * HD_ + nt * 8 + g]);
                unsigned b1 = __float_as_uint(Vs[(kk * 8 + tg + 4) * KV_STRIDE + h * HD_ + nt * 8 + g]);
                MMA_TF32(oacc[nt], a0, a1, a2, a3, b0, b1);
            }
        }
        __syncthreads();
    }

    la += __shfl_xor_sync(0xffffffffu, la, 1);
    la += __shfl_xor_sync(0xffffffffu, la, 2);
    lb += __shfl_xor_sync(0xffffffffu, lb, 1);
    lb += __shfl_xor_sync(0xffffffffu, lb, 2);
    float inva = 1.f / la, invb = 1.f / lb;

    float* orow_a = O + ((size_t)(b * L_ + q0 + g))     * D_ + h * HD_;
    float* orow_b = O + ((size_t)(b * L_ + q0 + g + 8)) * D_ + h * HD_;
#pragma unroll
    for (int nt = 0; nt < 4; nt++) {
        orow_a[nt * 8 + 2 * tg]     = oacc[nt][0] * inva;
        orow_a[nt * 8 + 2 * tg + 1] = oacc[nt][1] * inva;
        orow_b[nt * 8 + 2 * tg]     = oacc[nt][2] * invb;
        orow_b[nt * 8 + 2 * tg + 1] = oacc[nt][3] * invb;
    }
}

// ---------------- LN1 fused with concat materialization ----------------
__global__ void __launch_bounds__(256) ln_concat_kernel(const float* __restrict__ M1,
                                                        const float* __restrict__ x,
                                                        const float* __restrict__ g,
                                                        const float* __restrict__ b,
                                                        float* __restrict__ Hin) {
    int warp = threadIdx.x >> 5, lane = threadIdx.x & 31;
    int row = blockIdx.x * 8 + warp;
    const float* p = M1 + (size_t)row * D_;
    float v[8]; float s = 0.f;
#pragma unroll
    for (int k = 0; k < 8; k++) { v[k] = p[lane + 32 * k]; s += v[k]; }
#pragma unroll
    for (int o = 16; o; o >>= 1) s += __shfl_xor_sync(0xffffffffu, s, o);
    float mean = s * (1.f / 256.f);
    float vs = 0.f;
#pragma unroll
    for (int k = 0; k < 8; k++) { float d = v[k] - mean; vs += d * d; }
#pragma unroll
    for (int o = 16; o; o >>= 1) vs += __shfl_xor_sync(0xffffffffu, vs, o);
    float rstd = rsqrtf(vs * (1.f / 256.f) + 1e-5f);
    float* ho = Hin + (size_t)row * (2 * D_);
    const float* xr = x + (size_t)row * D_;
#pragma unroll
    for (int k = 0; k < 8; k++) {
        int col = lane + 32 * k;
        ho[col]      = xr[col];
        ho[D_ + col] = (v[k] - mean) * rstd * g[col] + b[col];
    }
}

// ---------------- LN2 + residual, writes final output ----------------
__global__ void __launch_bounds__(256) ln_residual_kernel(const float* __restrict__ M2,
                                                          const float* __restrict__ x,
                                                          const float* __restrict__ g,
                                                          const float* __restrict__ b,
                                                          float* __restrict__ out) {
    int warp = threadIdx.x >> 5, lane = threadIdx.x & 31;
    int row = blockIdx.x * 8 + warp;
    const float* p = M2 + (size_t)row * D_;
    float v[8]; float s = 0.f;
#pragma unroll
    for (int k = 0; k < 8; k++) { v[k] = p[lane + 32 * k]; s += v[k]; }
#pragma unroll
    for (int o = 16; o; o >>= 1) s += __shfl_xor_sync(0xffffffffu, s, o);
    float mean = s * (1.f / 256.f);
    float vs = 0.f;
#pragma unroll
    for (int k = 0; k < 8; k++) { float d = v[k] - mean; vs += d * d; }
#pragma unroll
    for (int o = 16; o; o >>= 1) vs += __shfl_xor_sync(0xffffffffu, vs, o);
    float rstd = rsqrtf(vs * (1.f / 256.f) + 1e-5f);
    const float* xr = x + (size_t)row * D_;
    float* orow = out + (size_t)row * D_;
#pragma unroll
    for (int k = 0; k < 8; k++) {
        int col = lane + 32 * k;
        orow[col] = xr[col] + (v[k] - mean) * rstd * g[col] + b[col];
    }
}

// ---------------- launch ----------------
extern "C" void kernel_launch(void* const* d_in, const int* in_sizes, int n_in,
                              void* d_out, int out_size) {
    const float* x   = (const float*)d_in[0];
    const float* src = (const float*)d_in[1];
    const float* af  = (const float*)d_in[2];
    const float* Wq  = (const float*)d_in[3];
    const float* Wk  = (const float*)d_in[4];
    const float* Wv  = (const float*)d_in[5];
    const float* Wm  = (const float*)d_in[6];
    const float* W1  = (const float*)d_in[7];
    const float* W2  = (const float*)d_in[8];
    const float* g1  = (const float*)d_in[9];
    const float* b1  = (const float*)d_in[10];
    const float* g2  = (const float*)d_in[11];
    const float* b2  = (const float*)d_in[12];
    float* out = (float*)d_out;

    float *Qp, *Kp, *Vp, *Op, *M1p, *Hin, *Hre, *M2p;
    cudaGetSymbolAddress((void**)&Qp,  g_Q);
    cudaGetSymbolAddress((void**)&Kp,  g_K);
    cudaGetSymbolAddress((void**)&Vp,  g_V);
    cudaGetSymbolAddress((void**)&Op,  g_O);
    cudaGetSymbolAddress((void**)&M1p, g_M1);
    cudaGetSymbolAddress((void**)&Hin, g_Hin);
    cudaGetSymbolAddress((void**)&Hre, g_Hre);
    cudaGetSymbolAddress((void**)&M2p, g_M2);

    const int attn_smem = SMEM_ATTN_FLOATS * (int)sizeof(float);  // ~89 KB
    cudaFuncSetAttribute(attn_tc, cudaFuncAttributeMaxDynamicSharedMemorySize, attn_smem);

    // Q/K/V projections: tensor-core, one launch (384 CTAs)
    gemm_qkv_tc<<<dim3(D_ / 64, ROWS / 128, 3), 256>>>(x, src, Wq, Wk, Wv, Qp, Kp, Vp);
    // tensor-core flash attention, all heads per CTA
    attn_tc<<<dim3(L_ / 16, B_), 256, attn_smem>>>(Qp, Kp, Vp, af, Op);
    // message = O @ Wm^T   (BN=32 -> 256 CTAs)
    gemm_tc<32><<<dim3(D_ / 32, ROWS / 128), 256>>>(Op, Wm, M1p, D_, D_, 0);
    // LN1 + concat [x, ln(message)]
    ln_concat_kernel<<<ROWS / 8, 256>>>(M1p, x, g1, b1, Hin);
    // h = relu(Hin @ W1^T)  (BN=64 -> 256 CTAs)
    gemm_tc<64><<<dim3(2 * D_ / 64, ROWS / 128), 256>>>(Hin, W1, Hre, 2 * D_, 2 * D_, 1);
    // M2 = h @ W2^T  (BN=32 -> 256 CTAs)
    gemm_tc<32><<<dim3(D_ / 32, ROWS / 128), 256>>>(Hre, W2, M2p, D_, 2 * D_, 0);
    // out = x + LN2(M2)
    ln_residual_kernel<<<ROWS / 8, 256>>>(M2p, x, g2, b2, out);
}

// round 15
// speedup vs baseline: 2.2706x; 1.1978x over previous
#include <cuda_runtime.h>
#include <math.h>

#define B_  2
#define L_  2048
#define S_  2048
#define D_  256
#define H_  8
#define HD_ 32
#define ROWS (B_*L_)      // 4096
#define NSPLIT 2
#define SKEYS (S_/NSPLIT) // 1024
#define QT 32             // queries per attention CTA

// ---------------- scratch (no allocations allowed) ----------------
__device__ float g_Q   [ROWS*D_];
__device__ float g_K   [ROWS*D_];
__device__ float g_V   [ROWS*D_];
__device__ float g_O   [ROWS*D_];
__device__ float g_M1  [ROWS*D_];
__device__ float g_Hin [ROWS*2*D_];
__device__ float g_Hre [ROWS*2*D_];
__device__ float g_M2  [ROWS*D_];
__device__ float g_pacc[B_*H_*NSPLIT*L_*HD_];  // [bh][sp][q][d] unnormalized
__device__ float g_pml [B_*H_*NSPLIT*2*L_];    // [bh][sp][{m,l}][q]

// ---------------- tf32 / async helpers ----------------
__device__ __forceinline__ unsigned f2tf(float x) {
    unsigned u;
    asm("cvt.rna.tf32.f32 %0, %1;" : "=r"(u) : "f"(x));
    return u;
}
__device__ __forceinline__ float f2tf_f(float x) { return __uint_as_float(f2tf(x)); }

__device__ __forceinline__ void cp_async16(unsigned smem_addr, const void* gptr) {
    asm volatile("cp.async.cg.shared.global [%0], [%1], 16;" :: "r"(smem_addr), "l"(gptr));
}
__device__ __forceinline__ void cp_async_commit_wait() {
    asm volatile("cp.async.commit_group;");
    asm volatile("cp.async.wait_group 0;");
}

#define MMA_TF32(d, a0, a1, a2, a3, b0, b1)                                    \
    asm volatile("mma.sync.aligned.m16n8k8.row.col.f32.tf32.tf32.f32 "         \
                 "{%0,%1,%2,%3},{%4,%5,%6,%7},{%8,%9},{%0,%1,%2,%3};"          \
                 : "+f"(d[0]), "+f"(d[1]), "+f"(d[2]), "+f"(d[3])              \
                 : "r"(a0), "r"(a1), "r"(a2), "r"(a3), "r"(b0), "r"(b1))

// ============== tf32 tensor-core GEMM: C[M,N] = A[M,K] @ W[N,K]^T ============
// Block tile 128 x BN, 256 threads (8 warps). Warp tile 32 x (BN/2).
// Smem stride 36 floats -> conflict-free fragment reads. round_out=1 writes
// tf32-rounded outputs (used for Q/K/V so attention staging is a pure copy).
template<int BN>
__device__ __forceinline__ void gemm_tc_body(const float* __restrict__ A,
                                             const float* __restrict__ W,
                                             float* __restrict__ C,
                                             int N, int K, int relu, int round_out,
                                             int m0, int n0) {
    __shared__ float As[128][36];
    __shared__ float Bs[BN][36];
    constexpr int NT = BN / 16;
    const int tid  = threadIdx.x;
    const int w    = tid >> 5, lane = tid & 31;
    const int g    = lane >> 2, tg = lane & 3;
    const int mw   = (w >> 1) * 32;
    const int nw   = (w & 1) * (BN / 2);

    float acc[2][NT][4];
#pragma unroll
    for (int mi = 0; mi < 2; mi++)
#pragma unroll
        for (int nt = 0; nt < NT; nt++)
#pragma unroll
            for (int i = 0; i < 4; i++) acc[mi][nt][i] = 0.f;

    for (int k0 = 0; k0 < K; k0 += 32) {
#pragma unroll
        for (int it = 0; it < 4; it++) {
            int idx = tid + it * 256;
            int r = idx >> 3, c = (idx & 7) * 4;
            float4 a = *(const float4*)(A + (size_t)(m0 + r) * K + k0 + c);
            a.x = f2tf_f(a.x); a.y = f2tf_f(a.y); a.z = f2tf_f(a.z); a.w = f2tf_f(a.w);
            *(float4*)(&As[r][c]) = a;
        }
#pragma unroll
        for (int it = 0; it < BN / 32; it++) {
            int idx = tid + it * 256;
            int r = idx >> 3, c = (idx & 7) * 4;
            float4 b = *(const float4*)(W + (size_t)(n0 + r) * K + k0 + c);
            b.x = f2tf_f(b.x); b.y = f2tf_f(b.y); b.z = f2tf_f(b.z); b.w = f2tf_f(b.w);
            *(float4*)(&Bs[r][c]) = b;
        }
        __syncthreads();

#pragma unroll
        for (int kk = 0; kk < 4; kk++) {
            unsigned af[2][4];
#pragma unroll
            for (int mi = 0; mi < 2; mi++) {
                int mr = mw + mi * 16;
                af[mi][0] = __float_as_uint(As[mr + g    ][kk * 8 + tg]);
                af[mi][1] = __float_as_uint(As[mr + g + 8][kk * 8 + tg]);
                af[mi][2] = __float_as_uint(As[mr + g    ][kk * 8 + tg + 4]);
                af[mi][3] = __float_as_uint(As[mr + g + 8][kk * 8 + tg + 4]);
            }
            unsigned bf[NT][2];
#pragma unroll
            for (int nt = 0; nt < NT; nt++) {
                bf[nt][0] = __float_as_uint(Bs[nw + nt * 8 + g][kk * 8 + tg]);
                bf[nt][1] = __float_as_uint(Bs[nw + nt * 8 + g][kk * 8 + tg + 4]);
            }
#pragma unroll
            for (int mi = 0; mi < 2; mi++)
#pragma unroll
                for (int nt = 0; nt < NT; nt++)
                    MMA_TF32(acc[mi][nt], af[mi][0], af[mi][1], af[mi][2], af[mi][3],
                             bf[nt][0], bf[nt][1]);
        }
        __syncthreads();
    }

#pragma unroll
    for (int mi = 0; mi < 2; mi++) {
        int row0 = m0 + mw + mi * 16 + g;
#pragma unroll
        for (int nt = 0; nt < NT; nt++) {
            int col = n0 + nw + nt * 8 + 2 * tg;
            float2 v0 = make_float2(acc[mi][nt][0], acc[mi][nt][1]);
            float2 v1 = make_float2(acc[mi][nt][2], acc[mi][nt][3]);
            if (relu) {
                v0.x = fmaxf(v0.x, 0.f); v0.y = fmaxf(v0.y, 0.f);
                v1.x = fmaxf(v1.x, 0.f); v1.y = fmaxf(v1.y, 0.f);
            }
            if (round_out) {
                v0.x = f2tf_f(v0.x); v0.y = f2tf_f(v0.y);
                v1.x = f2tf_f(v1.x); v1.y = f2tf_f(v1.y);
            }
            *(float2*)(C + (size_t)row0 * N + col)       = v0;
            *(float2*)(C + (size_t)(row0 + 8) * N + col) = v1;
        }
    }
}

template<int BN>
__global__ void __launch_bounds__(256) gemm_tc(const float* __restrict__ A,
                                               const float* __restrict__ W,
                                               float* __restrict__ C,
                                               int N, int K, int relu) {
    gemm_tc_body<BN>(A, W, C, N, K, relu, 0, blockIdx.y * 128, blockIdx.x * BN);
}

// Q/K/V projections batched over blockIdx.z; outputs tf32-rounded.
__global__ void __launch_bounds__(256) gemm_qkv_tc(const float* __restrict__ x,
                                                   const float* __restrict__ src,
                                                   const float* __restrict__ Wq,
                                                   const float* __restrict__ Wk,
                                                   const float* __restrict__ Wv,
                                                   float* __restrict__ Q,
                                                   float* __restrict__ K,
                                                   float* __restrict__ V) {
    const float* A; const float* W; float* C;
    if (blockIdx.z == 0)      { A = x;   W = Wq; C = Q; }
    else if (blockIdx.z == 1) { A = src; W = Wk; C = K; }
    else                      { A = src; W = Wv; C = V; }
    gemm_tc_body<64>(A, W, C, D_, D_, 0, 1, blockIdx.y * 128, blockIdx.x * 64);
}

// ====== tensor-core flash attention: 32q/CTA, split-KV, cp.async staging =====
// grid (L/32, B, NSPLIT), 256 threads; warp w = head w (2 m-tiles of 16q).
// Q/K/V already tf32-rounded in gmem -> staging is pure 16B async copies.
#define KV_STRIDE 268
#define AF_STRIDE 36
#define SMEM_ATTN_FLOATS (2*32*KV_STRIDE + QT*AF_STRIDE + 8*16*AF_STRIDE)

__global__ void __launch_bounds__(256, 2) attn_tc(const float* __restrict__ Q,
                                                  const float* __restrict__ K,
                                                  const float* __restrict__ V,
                                                  const float* __restrict__ AF,
                                                  float* __restrict__ pacc,
                                                  float* __restrict__ pml) {
    extern __shared__ float sm[];
    float* Ks  = sm;
    float* Vs  = sm + 32 * KV_STRIDE;
    float* AFs = Vs + 32 * KV_STRIDE;
    float* Ps  = AFs + QT * AF_STRIDE;

    const int b   = blockIdx.y;
    const int sp  = blockIdx.z;
    const int q0  = blockIdx.x * QT;
    const int tid = threadIdx.x;
    const int w   = tid >> 5;
    const int lane = tid & 31;
    const int g  = lane >> 2;
    const int tg = lane & 3;
    const int h  = w;
    const int bh = b * H_ + h;
    const float scale = 0.17677669529663687f;  // 1/sqrt(32)

    const unsigned ks_base = (unsigned)__cvta_generic_to_shared(Ks);
    const unsigned vs_base = (unsigned)__cvta_generic_to_shared(Vs);
    const unsigned af_base = (unsigned)__cvta_generic_to_shared(AFs);

    // Q fragments for 2 m-tiles (pre-rounded tf32 in gmem)
    unsigned qa[2][4][4];
    {
        const float* qb = Q + ((size_t)(b * L_ + q0)) * D_ + h * HD_;
#pragma unroll
        for (int mi = 0; mi < 2; mi++)
#pragma unroll
            for (int kk = 0; kk < 4; kk++) {
                qa[mi][kk][0] = __float_as_uint(qb[(size_t)(mi*16 + g)     * D_ + kk*8 + tg]);
                qa[mi][kk][1] = __float_as_uint(qb[(size_t)(mi*16 + g + 8) * D_ + kk*8 + tg]);
                qa[mi][kk][2] = __float_as_uint(qb[(size_t)(mi*16 + g)     * D_ + kk*8 + tg + 4]);
                qa[mi][kk][3] = __float_as_uint(qb[(size_t)(mi*16 + g + 8) * D_ + kk*8 + tg + 4]);
            }
    }

    float mA[2] = {-3.0e38f, -3.0e38f}, mB[2] = {-3.0e38f, -3.0e38f};
    float lA[2] = {0.f, 0.f},           lB[2] = {0.f, 0.f};
    float oacc[2][4][4];
#pragma unroll
    for (int mi = 0; mi < 2; mi++)
#pragma unroll
        for (int nt = 0; nt < 4; nt++)
#pragma unroll
            for (int i = 0; i < 4; i++) oacc[mi][nt][i] = 0.f;

    float* Pw = Ps + w * (16 * AF_STRIDE);
    const int s_begin = sp * SKEYS;

    for (int s0 = s_begin; s0 < s_begin + SKEYS; s0 += 32) {
        // --- async stage: K,V (32 rows x 256 cols) + AF (32 x 32) ---
        const float* Kb = K + ((size_t)(b * S_ + s0)) * D_;
        const float* Vb = V + ((size_t)(b * S_ + s0)) * D_;
#pragma unroll
        for (int i = 0; i < 8; i++) {
            int idx = tid + i * 256;
            int r = idx >> 6, c4 = (idx & 63) * 4;
            cp_async16(ks_base + (r * KV_STRIDE + c4) * 4, Kb + (size_t)r * D_ + c4);
            cp_async16(vs_base + (r * KV_STRIDE + c4) * 4, Vb + (size_t)r * D_ + c4);
        }
        {
            int r = tid >> 3, c4 = (tid & 7) * 4;
            cp_async16(af_base + (r * AF_STRIDE + c4) * 4,
                       AF + ((size_t)(b * L_ + q0 + r)) * S_ + s0 + c4);
        }
        cp_async_commit_wait();
        __syncthreads();

#pragma unroll
        for (int mi = 0; mi < 2; mi++) {
            // --- S = Q K^T for this m-tile: [16 x 32] ---
            float sc[4][4];
#pragma unroll
            for (int nt = 0; nt < 4; nt++) { sc[nt][0]=0.f; sc[nt][1]=0.f; sc[nt][2]=0.f; sc[nt][3]=0.f; }
#pragma unroll
            for (int kk = 0; kk < 4; kk++) {
#pragma unroll
                for (int nt = 0; nt < 4; nt++) {
                    unsigned b0 = __float_as_uint(Ks[(nt*8 + g) * KV_STRIDE + h*HD_ + kk*8 + tg]);
                    unsigned b1 = __float_as_uint(Ks[(nt*8 + g) * KV_STRIDE + h*HD_ + kk*8 + tg + 4]);
                    MMA_TF32(sc[nt], qa[mi][kk][0], qa[mi][kk][1], qa[mi][kk][2], qa[mi][kk][3], b0, b1);
                }
            }
            float mxa = -3.0e38f, mxb = -3.0e38f;
#pragma unroll
            for (int nt = 0; nt < 4; nt++) {
                int ra = (mi*16 + g) * AF_STRIDE, rb = (mi*16 + g + 8) * AF_STRIDE;
                sc[nt][0] *= scale * AFs[ra + nt*8 + 2*tg];
                sc[nt][1] *= scale * AFs[ra + nt*8 + 2*tg + 1];
                sc[nt][2] *= scale * AFs[rb + nt*8 + 2*tg];
                sc[nt][3] *= scale * AFs[rb + nt*8 + 2*tg + 1];
                mxa = fmaxf(mxa, fmaxf(sc[nt][0], sc[nt][1]));
                mxb = fmaxf(mxb, fmaxf(sc[nt][2], sc[nt][3]));
            }
            mxa = fmaxf(mxa, __shfl_xor_sync(0xffffffffu, mxa, 1));
            mxa = fmaxf(mxa, __shfl_xor_sync(0xffffffffu, mxa, 2));
            mxb = fmaxf(mxb, __shfl_xor_sync(0xffffffffu, mxb, 1));
            mxb = fmaxf(mxb, __shfl_xor_sync(0xffffffffu, mxb, 2));

            float mna = fmaxf(mA[mi], mxa), mnb = fmaxf(mB[mi], mxb);
            float ca = __expf(mA[mi] - mna), cb = __expf(mB[mi] - mnb);
            mA[mi] = mna; mB[mi] = mnb;

            float pa = 0.f, pb = 0.f;
#pragma unroll
            for (int nt = 0; nt < 4; nt++) {
                float p0 = f2tf_f(__expf(sc[nt][0] - mna));
                float p1 = f2tf_f(__expf(sc[nt][1] - mna));
                float p2 = f2tf_f(__expf(sc[nt][2] - mnb));
                float p3 = f2tf_f(__expf(sc[nt][3] - mnb));
                pa += p0 + p1; pb += p2 + p3;
                Pw[g * AF_STRIDE + nt*8 + 2*tg]           = p0;
                Pw[g * AF_STRIDE + nt*8 + 2*tg + 1]       = p1;
                Pw[(g + 8) * AF_STRIDE + nt*8 + 2*tg]     = p2;
                Pw[(g + 8) * AF_STRIDE + nt*8 + 2*tg + 1] = p3;
            }
            lA[mi] = lA[mi] * ca + pa;
            lB[mi] = lB[mi] * cb + pb;
#pragma unroll
            for (int nt = 0; nt < 4; nt++) {
                oacc[mi][nt][0] *= ca; oacc[mi][nt][1] *= ca;
                oacc[mi][nt][2] *= cb; oacc[mi][nt][3] *= cb;
            }
            __syncwarp();

            // --- O_mi += P V : [16 x 32], k = 32 keys ---
#pragma unroll
            for (int kk = 0; kk < 4; kk++) {
                unsigned a0 = __float_as_uint(Pw[g * AF_STRIDE + kk*8 + tg]);
                unsigned a1 = __float_as_uint(Pw[(g + 8) * AF_STRIDE + kk*8 + tg]);
                unsigned a2 = __float_as_uint(Pw[g * AF_STRIDE + kk*8 + tg + 4]);
                unsigned a3 = __float_as_uint(Pw[(g + 8) * AF_STRIDE + kk*8 + tg + 4]);
#pragma unroll
                for (int nt = 0; nt < 4; nt++) {
                    unsigned b0 = __float_as_uint(Vs[(kk*8 + tg)     * KV_STRIDE + h*HD_ + nt*8 + g]);
                    unsigned b1 = __float_as_uint(Vs[(kk*8 + tg + 4) * KV_STRIDE + h*HD_ + nt*8 + g]);
                    MMA_TF32(oacc[mi][nt], a0, a1, a2, a3, b0, b1);
                }
            }
            __syncwarp();   // Pw reused by next m-tile
        }
        __syncthreads();
    }

    // --- FIX (R9 bug): reduce l across the 4 threads of each MMA group ---
    // Each thread's lA/lB only sums its own 8 of 32 columns per row; the row
    // denominator needs the full sum before the partial write.
#pragma unroll
    for (int mi = 0; mi < 2; mi++) {
        lA[mi] += __shfl_xor_sync(0xffffffffu, lA[mi], 1);
        lA[mi] += __shfl_xor_sync(0xffffffffu, lA[mi], 2);
        lB[mi] += __shfl_xor_sync(0xffffffffu, lB[mi], 1);
        lB[mi] += __shfl_xor_sync(0xffffffffu, lB[mi], 2);
    }

    // --- write unnormalized partials + (m,l) ---
#pragma unroll
    for (int mi = 0; mi < 2; mi++) {
        int qa_row = q0 + mi*16 + g;
        float* pr0 = pacc + ((size_t)(bh * NSPLIT + sp) * L_ + qa_row) * HD_;
        float* pr1 = pr0 + 8 * HD_;
#pragma unroll
        for (int nt = 0; nt < 4; nt++) {
            *(float2*)(pr0 + nt*8 + 2*tg) = make_float2(oacc[mi][nt][0], oacc[mi][nt][1]);
            *(float2*)(pr1 + nt*8 + 2*tg) = make_float2(oacc[mi][nt][2], oacc[mi][nt][3]);
        }
        if (tg == 0) {
            float* pm = pml + ((size_t)(bh * NSPLIT + sp) * 2) * L_;
            pm[qa_row]          = mA[mi];
            pm[qa_row + 8]      = mB[mi];
            pm[L_ + qa_row]     = lA[mi];
            pm[L_ + qa_row + 8] = lB[mi];
        }
    }
}

// merge the NSPLIT=2 partial online-softmax states; warp = one (bh, q) row
__global__ void __launch_bounds__(256) attn_combine(const float* __restrict__ pacc,
                                                    const float* __restrict__ pml,
                                                    float* __restrict__ O) {
    const int bh = blockIdx.y;
    const int b  = bh >> 3;
    const int h  = bh & 7;
    const int q  = blockIdx.x * 8 + (threadIdx.x >> 5);
    const int d  = threadIdx.x & 31;

    const float* pm0 = pml + ((size_t)(bh * NSPLIT + 0) * 2) * L_;
    const float* pm1 = pml + ((size_t)(bh * NSPLIT + 1) * 2) * L_;
    float m0 = pm0[q], l0 = pm0[L_ + q];
    float m1 = pm1[q], l1 = pm1[L_ + q];
    float M  = fmaxf(m0, m1);
    float w0 = __expf(m0 - M), w1 = __expf(m1 - M);
    float inv = 1.f / (l0 * w0 + l1 * w1);

    float a0 = pacc[((size_t)(bh * NSPLIT + 0) * L_ + q) * HD_ + d];
    float a1 = pacc[((size_t)(bh * NSPLIT + 1) * L_ + q) * HD_ + d];
    O[((size_t)(b * L_ + q)) * D_ + h * HD_ + d] = (a0 * w0 + a1 * w1) * inv;
}

// ---------------- LN1 fused with concat materialization ----------------
__global__ void __launch_bounds__(256) ln_concat_kernel(const float* __restrict__ M1,
                                                        const float* __restrict__ x,
                                                        const float* __restrict__ g,
                                                        const float* __restrict__ b,
                                                        float* __restrict__ Hin) {
    int warp = threadIdx.x >> 5, lane = threadIdx.x & 31;
    int row = blockIdx.x * 8 + warp;
    const float* p = M1 + (size_t)row * D_;
    float v[8]; float s = 0.f;
#pragma unroll
    for (int k = 0; k < 8; k++) { v[k] = p[lane + 32 * k]; s += v[k]; }
#pragma unroll
    for (int o = 16; o; o >>= 1) s += __shfl_xor_sync(0xffffffffu, s, o);
    float mean = s * (1.f / 256.f);
    float vs = 0.f;
#pragma unroll
    for (int k = 0; k < 8; k++) { float d = v[k] - mean; vs += d * d; }
#pragma unroll
    for (int o = 16; o; o >>= 1) vs += __shfl_xor_sync(0xffffffffu, vs, o);
    float rstd = rsqrtf(vs * (1.f / 256.f) + 1e-5f);
    float* ho = Hin + (size_t)row * (2 * D_);
    const float* xr = x + (size_t)row * D_;
#pragma unroll
    for (int k = 0; k < 8; k++) {
        int col = lane + 32 * k;
        ho[col]      = xr[col];
        ho[D_ + col] = (v[k] - mean) * rstd * g[col] + b[col];
    }
}

// ---------------- LN2 + residual, writes final output ----------------
__global__ void __launch_bounds__(256) ln_residual_kernel(const float* __restrict__ M2,
                                                          const float* __restrict__ x,
                                                          const float* __restrict__ g,
                                                          const float* __restrict__ b,
                                                          float* __restrict__ out) {
    int warp = threadIdx.x >> 5, lane = threadIdx.x & 31;
    int row = blockIdx.x * 8 + warp;
    const float* p = M2 + (size_t)row * D_;
    float v[8]; float s = 0.f;
#pragma unroll
    for (int k = 0; k < 8; k++) { v[k] = p[lane + 32 * k]; s += v[k]; }
#pragma unroll
    for (int o = 16; o; o >>= 1) s += __shfl_xor_sync(0xffffffffu, s, o);
    float mean = s * (1.f / 256.f);
    float vs = 0.f;
#pragma unroll
    for (int k = 0; k < 8; k++) { float d = v[k] - mean; vs += d * d; }
#pragma unroll
    for (int o = 16; o; o >>= 1) vs += __shfl_xor_sync(0xffffffffu, vs, o);
    float rstd = rsqrtf(vs * (1.f / 256.f) + 1e-5f);
    const float* xr = x + (size_t)row * D_;
    float* orow = out + (size_t)row * D_;
#pragma unroll
    for (int k = 0; k < 8; k++) {
        int col = lane + 32 * k;
        orow[col] = xr[col] + (v[k] - mean) * rstd * g[col] + b[col];
    }
}

// ---------------- launch ----------------
extern "C" void kernel_launch(void* const* d_in, const int* in_sizes, int n_in,
                              void* d_out, int out_size) {
    const float* x   = (const float*)d_in[0];
    const float* src = (const float*)d_in[1];
    const float* af  = (const float*)d_in[2];
    const float* Wq  = (const float*)d_in[3];
    const float* Wk  = (const float*)d_in[4];
    const float* Wv  = (const float*)d_in[5];
    const float* Wm  = (const float*)d_in[6];
    const float* W1  = (const float*)d_in[7];
    const float* W2  = (const float*)d_in[8];
    const float* g1  = (const float*)d_in[9];
    const float* b1  = (const float*)d_in[10];
    const float* g2  = (const float*)d_in[11];
    const float* b2  = (const float*)d_in[12];
    float* out = (float*)d_out;

    float *Qp, *Kp, *Vp, *Op, *M1p, *Hin, *Hre, *M2p, *pacc, *pml;
    cudaGetSymbolAddress((void**)&Qp,   g_Q);
    cudaGetSymbolAddress((void**)&Kp,   g_K);
    cudaGetSymbolAddress((void**)&Vp,   g_V);
    cudaGetSymbolAddress((void**)&Op,   g_O);
    cudaGetSymbolAddress((void**)&M1p,  g_M1);
    cudaGetSymbolAddress((void**)&Hin,  g_Hin);
    cudaGetSymbolAddress((void**)&Hre,  g_Hre);
    cudaGetSymbolAddress((void**)&M2p,  g_M2);
    cudaGetSymbolAddress((void**)&pacc, g_pacc);
    cudaGetSymbolAddress((void**)&pml,  g_pml);

    const int attn_smem = SMEM_ATTN_FLOATS * (int)sizeof(float);  // ~91.6 KB
    cudaFuncSetAttribute(attn_tc, cudaFuncAttributeMaxDynamicSharedMemorySize, attn_smem);

    // Q/K/V projections: tensor-core, tf32-rounded outputs (384 CTAs)
    gemm_qkv_tc<<<dim3(D_ / 64, ROWS / 128, 3), 256>>>(x, src, Wq, Wk, Wv, Qp, Kp, Vp);
    // flash attention: 32q/CTA, split-KV (256 CTAs, 2/SM), then combine
    attn_tc<<<dim3(L_ / QT, B_, NSPLIT), 256, attn_smem>>>(Qp, Kp, Vp, af, pacc, pml);
    attn_combine<<<dim3(L_ / 8, B_ * H_), 256>>>(pacc, pml, Op);
    // message = O @ Wm^T
    gemm_tc<32><<<dim3(D_ / 32, ROWS / 128), 256>>>(Op, Wm, M1p, D_, D_, 0);
    // LN1 + concat [x, ln(message)]
    ln_concat_kernel<<<ROWS / 8, 256>>>(M1p, x, g1, b1, Hin);
    // h = relu(Hin @ W1^T)
    gemm_tc<64><<<dim3(2 * D_ / 64, ROWS / 128), 256>>>(Hin, W1, Hre, 2 * D_, 2 * D_, 1);
    // M2 = h @ W2^T
    gemm_tc<32><<<dim3(D_ / 32, ROWS / 128), 256>>>(Hre, W2, M2p, D_, 2 * D_, 0);
    // out = x + LN2(M2)
    ln_residual_kernel<<<ROWS / 8, 256>>>(M2p, x, g2, b2, out);
}

// round 16
// speedup vs baseline: 2.5357x; 1.1167x over previous
#include <cuda_runtime.h>
#include <math.h>

#define B_  2
#define L_  2048
#define S_  2048
#define D_  256
#define H_  8
#define HD_ 32
#define ROWS (B_*L_)      // 4096
#define NSPLIT 2
#define SKEYS (S_/NSPLIT) // 1024
#define QT 64             // queries per attention CTA (4 m-tiles of 16)
#define KV2 132           // K/V smem stride (128 cols + 4 pad)
#define AF2 36            // AF / P smem stride

// ---------------- scratch (no allocations allowed) ----------------
__device__ float g_Q   [ROWS*D_];
__device__ float g_K   [ROWS*D_];
__device__ float g_V   [ROWS*D_];
__device__ float g_O   [ROWS*D_];
__device__ float g_M1  [ROWS*D_];
__device__ float g_Hin [ROWS*2*D_];
__device__ float g_Hre [ROWS*2*D_];
__device__ float g_M2  [ROWS*D_];
__device__ float g_pacc[B_*H_*NSPLIT*L_*HD_];  // [bh][sp][q][d] unnormalized
__device__ float g_pml [B_*H_*NSPLIT*2*L_];    // [bh][sp][{m,l}][q]

// ---------------- tf32 / async helpers ----------------
__device__ __forceinline__ unsigned f2tf(float x) {
    unsigned u;
    asm("cvt.rna.tf32.f32 %0, %1;" : "=r"(u) : "f"(x));
    return u;
}
__device__ __forceinline__ float f2tf_f(float x) { return __uint_as_float(f2tf(x)); }

__device__ __forceinline__ void cp_async16(unsigned smem_addr, const void* gptr) {
    asm volatile("cp.async.cg.shared.global [%0], [%1], 16;" :: "r"(smem_addr), "l"(gptr));
}

#define MMA_TF32(d, a0, a1, a2, a3, b0, b1)                                    \
    asm volatile("mma.sync.aligned.m16n8k8.row.col.f32.tf32.tf32.f32 "         \
                 "{%0,%1,%2,%3},{%4,%5,%6,%7},{%8,%9},{%0,%1,%2,%3};"          \
                 : "+f"(d[0]), "+f"(d[1]), "+f"(d[2]), "+f"(d[3])              \
                 : "r"(a0), "r"(a1), "r"(a2), "r"(a3), "r"(b0), "r"(b1))

// ============== tf32 tensor-core GEMM: C[M,N] = A[M,K] @ W[N,K]^T ============
// Block tile 128 x BN, 256 threads (8 warps). Warp tile 32 x (BN/2).
// Register-prefetch double buffering: next k-tile's LDGs issue before the MMA
// block (latency hidden behind compute), STS into the alternate smem stage.
template<int BN>
__device__ __forceinline__ void gemm_tc_body(const float* __restrict__ A,
                                             const float* __restrict__ W,
                                             float* __restrict__ C,
                                             int N, int K, int relu, int round_out,
                                             int m0, int n0) {
    __shared__ float As[2][128][36];
    __shared__ float Bs[2][BN][36];
    constexpr int NT = BN / 16;
    constexpr int NB = BN / 32;
    const int tid  = threadIdx.x;
    const int w    = tid >> 5, lane = tid & 31;
    const int g    = lane >> 2, tg = lane & 3;
    const int mw   = (w >> 1) * 32;
    const int nw   = (w & 1) * (BN / 2);

    float acc[2][NT][4];
#pragma unroll
    for (int mi = 0; mi < 2; mi++)
#pragma unroll
        for (int nt = 0; nt < NT; nt++)
#pragma unroll
            for (int i = 0; i < 4; i++) acc[mi][nt][i] = 0.f;

    float4 ra[4], rb[NB];

    auto ldg_tile = [&](int k0) {
#pragma unroll
        for (int it = 0; it < 4; it++) {
            int idx = tid + it * 256;
            ra[it] = *(const float4*)(A + (size_t)(m0 + (idx >> 3)) * K + k0 + (idx & 7) * 4);
        }
#pragma unroll
        for (int it = 0; it < NB; it++) {
            int idx = tid + it * 256;
            rb[it] = *(const float4*)(W + (size_t)(n0 + (idx >> 3)) * K + k0 + (idx & 7) * 4);
        }
    };
    auto sts_tile = [&](int st) {
#pragma unroll
        for (int it = 0; it < 4; it++) {
            int idx = tid + it * 256;
            int r = idx >> 3, c = (idx & 7) * 4;
            float4 a = ra[it];
            a.x = f2tf_f(a.x); a.y = f2tf_f(a.y); a.z = f2tf_f(a.z); a.w = f2tf_f(a.w);
            *(float4*)(&As[st][r][c]) = a;
        }
#pragma unroll
        for (int it = 0; it < NB; it++) {
            int idx = tid + it * 256;
            int r = idx >> 3, c = (idx & 7) * 4;
            float4 b = rb[it];
            b.x = f2tf_f(b.x); b.y = f2tf_f(b.y); b.z = f2tf_f(b.z); b.w = f2tf_f(b.w);
            *(float4*)(&Bs[st][r][c]) = b;
        }
    };

    const int nk = K / 32;
    ldg_tile(0);
    sts_tile(0);
    __syncthreads();

    for (int ki = 0; ki < nk; ki++) {
        const int st = ki & 1;
        if (ki + 1 < nk) ldg_tile((ki + 1) * 32);   // in flight during MMAs

#pragma unroll
        for (int kk = 0; kk < 4; kk++) {
            unsigned af[2][4];
#pragma unroll
            for (int mi = 0; mi < 2; mi++) {
                int mr = mw + mi * 16;
                af[mi][0] = __float_as_uint(As[st][mr + g    ][kk * 8 + tg]);
                af[mi][1] = __float_as_uint(As[st][mr + g + 8][kk * 8 + tg]);
                af[mi][2] = __float_as_uint(As[st][mr + g    ][kk * 8 + tg + 4]);
                af[mi][3] = __float_as_uint(As[st][mr + g + 8][kk * 8 + tg + 4]);
            }
            unsigned bf[NT][2];
#pragma unroll
            for (int nt = 0; nt < NT; nt++) {
                bf[nt][0] = __float_as_uint(Bs[st][nw + nt * 8 + g][kk * 8 + tg]);
                bf[nt][1] = __float_as_uint(Bs[st][nw + nt * 8 + g][kk * 8 + tg + 4]);
            }
#pragma unroll
            for (int mi = 0; mi < 2; mi++)
#pragma unroll
                for (int nt = 0; nt < NT; nt++)
                    MMA_TF32(acc[mi][nt], af[mi][0], af[mi][1], af[mi][2], af[mi][3],
                             bf[nt][0], bf[nt][1]);
        }

        if (ki + 1 < nk) sts_tile(st ^ 1);
        __syncthreads();
    }

#pragma unroll
    for (int mi = 0; mi < 2; mi++) {
        int row0 = m0 + mw + mi * 16 + g;
#pragma unroll
        for (int nt = 0; nt < NT; nt++) {
            int col = n0 + nw + nt * 8 + 2 * tg;
            float2 v0 = make_float2(acc[mi][nt][0], acc[mi][nt][1]);
            float2 v1 = make_float2(acc[mi][nt][2], acc[mi][nt][3]);
            if (relu) {
                v0.x = fmaxf(v0.x, 0.f); v0.y = fmaxf(v0.y, 0.f);
                v1.x = fmaxf(v1.x, 0.f); v1.y = fmaxf(v1.y, 0.f);
            }
            if (round_out) {
                v0.x = f2tf_f(v0.x); v0.y = f2tf_f(v0.y);
                v1.x = f2tf_f(v1.x); v1.y = f2tf_f(v1.y);
            }
            *(float2*)(C + (size_t)row0 * N + col)       = v0;
            *(float2*)(C + (size_t)(row0 + 8) * N + col) = v1;
        }
    }
}

template<int BN>
__global__ void __launch_bounds__(256) gemm_tc(const float* __restrict__ A,
                                               const float* __restrict__ W,
                                               float* __restrict__ C,
                                               int N, int K, int relu) {
    gemm_tc_body<BN>(A, W, C, N, K, relu, 0, blockIdx.y * 128, blockIdx.x * BN);
}

// Q/K/V projections batched over blockIdx.z; outputs tf32-rounded.
__global__ void __launch_bounds__(256) gemm_qkv_tc(const float* __restrict__ x,
                                                   const float* __restrict__ src,
                                                   const float* __restrict__ Wq,
                                                   const float* __restrict__ Wk,
                                                   const float* __restrict__ Wv,
                                                   float* __restrict__ Q,
                                                   float* __restrict__ K,
                                                   float* __restrict__ V) {
    const float* A; const float* W; float* C;
    if (blockIdx.z == 0)      { A = x;   W = Wq; C = Q; }
    else if (blockIdx.z == 1) { A = src; W = Wk; C = K; }
    else                      { A = src; W = Wv; C = V; }
    gemm_tc_body<64>(A, W, C, D_, D_, 0, 1, blockIdx.y * 128, blockIdx.x * 64);
}

// == tensor-core flash attention: 64q/CTA, head-group split, 2-stage pipeline ==
// grid (L/64, B, NSPLIT*2): z = sp*2+... encodes split sp = z>>1 and head-group
// hg = z&1 (heads 4*hg..4*hg+3). 128 threads, warp w = head hg*4+w.
// Each CTA stages only its head-group's 128 columns of K/V; AF tile 64x32.
// Two smem stages; tile t+1's cp.async issue overlaps tile t's compute.
#define STAGE_FLOATS (2*32*KV2 + QT*AF2)          // K + V + AF per stage = 10752
#define SMEM_ATTN_FLOATS (2*STAGE_FLOATS + 4*16*AF2)  // + Ps = 23808 (95.2 KB)

__global__ void __launch_bounds__(128, 2) attn_tc(const float* __restrict__ Q,
                                                  const float* __restrict__ K,
                                                  const float* __restrict__ V,
                                                  const float* __restrict__ AF,
                                                  float* __restrict__ pacc,
                                                  float* __restrict__ pml) {
    extern __shared__ float sm[];
    float* Ps = sm + 2 * STAGE_FLOATS;

    const int b   = blockIdx.y;
    const int sp  = blockIdx.z >> 1;
    const int hg  = blockIdx.z & 1;
    const int q0  = blockIdx.x * QT;
    const int tid = threadIdx.x;          // 0..127
    const int w   = tid >> 5;             // 0..3
    const int lane = tid & 31;
    const int g  = lane >> 2;
    const int tg = lane & 3;
    const int h  = hg * 4 + w;
    const int bh = b * H_ + h;
    const float scale = 0.17677669529663687f;  // 1/sqrt(32)

    // Q fragments for 4 m-tiles (pre-rounded tf32 in gmem)
    unsigned qa[4][4][4];
    {
        const float* qb = Q + ((size_t)(b * L_ + q0)) * D_ + h * HD_;
#pragma unroll
        for (int mi = 0; mi < 4; mi++)
#pragma unroll
            for (int kk = 0; kk < 4; kk++) {
                qa[mi][kk][0] = __float_as_uint(qb[(size_t)(mi*16 + g)     * D_ + kk*8 + tg]);
                qa[mi][kk][1] = __float_as_uint(qb[(size_t)(mi*16 + g + 8) * D_ + kk*8 + tg]);
                qa[mi][kk][2] = __float_as_uint(qb[(size_t)(mi*16 + g)     * D_ + kk*8 + tg + 4]);
                qa[mi][kk][3] = __float_as_uint(qb[(size_t)(mi*16 + g + 8) * D_ + kk*8 + tg + 4]);
            }
    }

    float mA[4], mB[4], lA[4], lB[4];
    float oacc[4][4][4];
#pragma unroll
    for (int mi = 0; mi < 4; mi++) {
        mA[mi] = -3.0e38f; mB[mi] = -3.0e38f; lA[mi] = 0.f; lB[mi] = 0.f;
#pragma unroll
        for (int nt = 0; nt < 4; nt++)
#pragma unroll
            for (int i = 0; i < 4; i++) oacc[mi][nt][i] = 0.f;
    }

    float* Pw = Ps + w * (16 * AF2);
    const int s_begin = sp * SKEYS;
    const int ntile = SKEYS / 32;         // 32

    // stage tile (32 keys) starting at s0 into smem stage st
    auto stage_tile = [&](int s0, int st) {
        float* KsS  = sm + st * STAGE_FLOATS;
        float* VsS  = KsS + 32 * KV2;
        float* AFsS = VsS + 32 * KV2;
        unsigned ks  = (unsigned)__cvta_generic_to_shared(KsS);
        unsigned vs  = (unsigned)__cvta_generic_to_shared(VsS);
        unsigned afs = (unsigned)__cvta_generic_to_shared(AFsS);
        const float* Kb = K + ((size_t)(b * S_ + s0)) * D_ + hg * 128;
        const float* Vb = V + ((size_t)(b * S_ + s0)) * D_ + hg * 128;
#pragma unroll
        for (int i = 0; i < 8; i++) {                 // K,V: 32 rows x 32 float4
            int idx = tid + i * 128;
            int r = idx >> 5, c4 = (idx & 31) * 4;
            cp_async16(ks + (r * KV2 + c4) * 4, Kb + (size_t)r * D_ + c4);
            cp_async16(vs + (r * KV2 + c4) * 4, Vb + (size_t)r * D_ + c4);
        }
#pragma unroll
        for (int i = 0; i < 4; i++) {                 // AF: 64 rows x 8 float4
            int idx = tid + i * 128;
            int r = idx >> 3, c4 = (idx & 7) * 4;
            cp_async16(afs + (r * AF2 + c4) * 4,
                       AF + ((size_t)(b * L_ + q0 + r)) * S_ + s0 + c4);
        }
        asm volatile("cp.async.commit_group;");
    };

    stage_tile(s_begin, 0);

    for (int t = 0; t < ntile; t++) {
        const int st = t & 1;
        if (t + 1 < ntile) {
            stage_tile(s_begin + (t + 1) * 32, st ^ 1);
            asm volatile("cp.async.wait_group 1;");   // tile t's group done
        } else {
            asm volatile("cp.async.wait_group 0;");
        }
        __syncthreads();

        float* Ks  = sm + st * STAGE_FLOATS;
        float* Vs  = Ks + 32 * KV2;
        float* AFs = Vs + 32 * KV2;

#pragma unroll
        for (int mi = 0; mi < 4; mi++) {
            // --- S = Q K^T for this m-tile: [16 x 32] ---
            float sc[4][4];
#pragma unroll
            for (int nt = 0; nt < 4; nt++) { sc[nt][0]=0.f; sc[nt][1]=0.f; sc[nt][2]=0.f; sc[nt][3]=0.f; }
#pragma unroll
            for (int kk = 0; kk < 4; kk++) {
#pragma unroll
                for (int nt = 0; nt < 4; nt++) {
                    unsigned b0 = __float_as_uint(Ks[(nt*8 + g) * KV2 + w*HD_ + kk*8 + tg]);
                    unsigned b1 = __float_as_uint(Ks[(nt*8 + g) * KV2 + w*HD_ + kk*8 + tg + 4]);
                    MMA_TF32(sc[nt], qa[mi][kk][0], qa[mi][kk][1], qa[mi][kk][2], qa[mi][kk][3], b0, b1);
                }
            }
            float mxa = -3.0e38f, mxb = -3.0e38f;
#pragma unroll
            for (int nt = 0; nt < 4; nt++) {
                int ra = (mi*16 + g) * AF2, rb = (mi*16 + g + 8) * AF2;
                sc[nt][0] *= scale * AFs[ra + nt*8 + 2*tg];
                sc[nt][1] *= scale * AFs[ra + nt*8 + 2*tg + 1];
                sc[nt][2] *= scale * AFs[rb + nt*8 + 2*tg];
                sc[nt][3] *= scale * AFs[rb + nt*8 + 2*tg + 1];
                mxa = fmaxf(mxa, fmaxf(sc[nt][0], sc[nt][1]));
                mxb = fmaxf(mxb, fmaxf(sc[nt][2], sc[nt][3]));
            }
            mxa = fmaxf(mxa, __shfl_xor_sync(0xffffffffu, mxa, 1));
            mxa = fmaxf(mxa, __shfl_xor_sync(0xffffffffu, mxa, 2));
            mxb = fmaxf(mxb, __shfl_xor_sync(0xffffffffu, mxb, 1));
            mxb = fmaxf(mxb, __shfl_xor_sync(0xffffffffu, mxb, 2));

            float mna = fmaxf(mA[mi], mxa), mnb = fmaxf(mB[mi], mxb);
            float ca = __expf(mA[mi] - mna), cb = __expf(mB[mi] - mnb);
            mA[mi] = mna; mB[mi] = mnb;

            float pa = 0.f, pb = 0.f;
#pragma unroll
            for (int nt = 0; nt < 4; nt++) {
                float p0 = f2tf_f(__expf(sc[nt][0] - mna));
                float p1 = f2tf_f(__expf(sc[nt][1] - mna));
                float p2 = f2tf_f(__expf(sc[nt][2] - mnb));
                float p3 = f2tf_f(__expf(sc[nt][3] - mnb));
                pa += p0 + p1; pb += p2 + p3;
                Pw[g * AF2 + nt*8 + 2*tg]           = p0;
                Pw[g * AF2 + nt*8 + 2*tg + 1]       = p1;
                Pw[(g + 8) * AF2 + nt*8 + 2*tg]     = p2;
                Pw[(g + 8) * AF2 + nt*8 + 2*tg + 1] = p3;
            }
            lA[mi] = lA[mi] * ca + pa;
            lB[mi] = lB[mi] * cb + pb;
#pragma unroll
            for (int nt = 0; nt < 4; nt++) {
                oacc[mi][nt][0] *= ca; oacc[mi][nt][1] *= ca;
                oacc[mi][nt][2] *= cb; oacc[mi][nt][3] *= cb;
            }
            __syncwarp();

            // --- O_mi += P V : [16 x 32], k = 32 keys ---
#pragma unroll
            for (int kk = 0; kk < 4; kk++) {
                unsigned a0 = __float_as_uint(Pw[g * AF2 + kk*8 + tg]);
                unsigned a1 = __float_as_uint(Pw[(g + 8) * AF2 + kk*8 + tg]);
                unsigned a2 = __float_as_uint(Pw[g * AF2 + kk*8 + tg + 4]);
                unsigned a3 = __float_as_uint(Pw[(g + 8) * AF2 + kk*8 + tg + 4]);
#pragma unroll
                for (int nt = 0; nt < 4; nt++) {
                    unsigned b0 = __float_as_uint(Vs[(kk*8 + tg)     * KV2 + w*HD_ + nt*8 + g]);
                    unsigned b1 = __float_as_uint(Vs[(kk*8 + tg + 4) * KV2 + w*HD_ + nt*8 + g]);
                    MMA_TF32(oacc[mi][nt], a0, a1, a2, a3, b0, b1);
                }
            }
            __syncwarp();   // Pw reused by next m-tile
        }
        __syncthreads();    // stage st free for tile t+2's issue
    }

    // reduce l across the 4 threads of each MMA group (full row denominator)
#pragma unroll
    for (int mi = 0; mi < 4; mi++) {
        lA[mi] += __shfl_xor_sync(0xffffffffu, lA[mi], 1);
        lA[mi] += __shfl_xor_sync(0xffffffffu, lA[mi], 2);
        lB[mi] += __shfl_xor_sync(0xffffffffu, lB[mi], 1);
        lB[mi] += __shfl_xor_sync(0xffffffffu, lB[mi], 2);
    }

    // --- write unnormalized partials + (m,l) ---
#pragma unroll
    for (int mi = 0; mi < 4; mi++) {
        int qa_row = q0 + mi*16 + g;
        float* pr0 = pacc + ((size_t)(bh * NSPLIT + sp) * L_ + qa_row) * HD_;
        float* pr1 = pr0 + 8 * HD_;
#pragma unroll
        for (int nt = 0; nt < 4; nt++) {
            *(float2*)(pr0 + nt*8 + 2*tg) = make_float2(oacc[mi][nt][0], oacc[mi][nt][1]);
            *(float2*)(pr1 + nt*8 + 2*tg) = make_float2(oacc[mi][nt][2], oacc[mi][nt][3]);
        }
        if (tg == 0) {
            float* pm = pml + ((size_t)(bh * NSPLIT + sp) * 2) * L_;
            pm[qa_row]          = mA[mi];
            pm[qa_row + 8]      = mB[mi];
            pm[L_ + qa_row]     = lA[mi];
            pm[L_ + qa_row + 8] = lB[mi];
        }
    }
}

// merge the NSPLIT=2 partial online-softmax states; warp = one (bh, q) row
__global__ void __launch_bounds__(256) attn_combine(const float* __restrict__ pacc,
                                                    const float* __restrict__ pml,
                                                    float* __restrict__ O) {
    const int bh = blockIdx.y;
    const int b  = bh >> 3;
    const int h  = bh & 7;
    const int q  = blockIdx.x * 8 + (threadIdx.x >> 5);
    const int d  = threadIdx.x & 31;

    const float* pm0 = pml + ((size_t)(bh * NSPLIT + 0) * 2) * L_;
    const float* pm1 = pml + ((size_t)(bh * NSPLIT + 1) * 2) * L_;
    float m0 = pm0[q], l0 = pm0[L_ + q];
    float m1 = pm1[q], l1 = pm1[L_ + q];
    float M  = fmaxf(m0, m1);
    float w0 = __expf(m0 - M), w1 = __expf(m1 - M);
    float inv = 1.f / (l0 * w0 + l1 * w1);

    float a0 = pacc[((size_t)(bh * NSPLIT + 0) * L_ + q) * HD_ + d];
    float a1 = pacc[((size_t)(bh * NSPLIT + 1) * L_ + q) * HD_ + d];
    O[((size_t)(b * L_ + q)) * D_ + h * HD_ + d] = (a0 * w0 + a1 * w1) * inv;
}

// ---------------- LN1 fused with concat materialization ----------------
__global__ void __launch_bounds__(256) ln_concat_kernel(const float* __restrict__ M1,
                                                        const float* __restrict__ x,
                                                        const float* __restrict__ g,
                                                        const float* __restrict__ b,
                                                        float* __restrict__ Hin) {
    int warp = threadIdx.x >> 5, lane = threadIdx.x & 31;
    int row = blockIdx.x * 8 + warp;
    const float* p = M1 + (size_t)row * D_;
    float v[8]; float s = 0.f;
#pragma unroll
    for (int k = 0; k < 8; k++) { v[k] = p[lane + 32 * k]; s += v[k]; }
#pragma unroll
    for (int o = 16; o; o >>= 1) s += __shfl_xor_sync(0xffffffffu, s, o);
    float mean = s * (1.f / 256.f);
    float vs = 0.f;
#pragma unroll
    for (int k = 0; k < 8; k++) { float d = v[k] - mean; vs += d * d; }
#pragma unroll
    for (int o = 16; o; o >>= 1) vs += __shfl_xor_sync(0xffffffffu, vs, o);
    float rstd = rsqrtf(vs * (1.f / 256.f) + 1e-5f);
    float* ho = Hin + (size_t)row * (2 * D_);
    const float* xr = x + (size_t)row * D_;
#pragma unroll
    for (int k = 0; k < 8; k++) {
        int col = lane + 32 * k;
        ho[col]      = xr[col];
        ho[D_ + col] = (v[k] - mean) * rstd * g[col] + b[col];
    }
}

// ---------------- LN2 + residual, writes final output ----------------
__global__ void __launch_bounds__(256) ln_residual_kernel(const float* __restrict__ M2,
                                                          const float* __restrict__ x,
                                                          const float* __restrict__ g,
                                                          const float* __restrict__ b,
                                                          float* __restrict__ out) {
    int warp = threadIdx.x >> 5, lane = threadIdx.x & 31;
    int row = blockIdx.x * 8 + warp;
    const float* p = M2 + (size_t)row * D_;
    float v[8]; float s = 0.f;
#pragma unroll
    for (int k = 0; k < 8; k++) { v[k] = p[lane + 32 * k]; s += v[k]; }
#pragma unroll
    for (int o = 16; o; o >>= 1) s += __shfl_xor_sync(0xffffffffu, s, o);
    float mean = s * (1.f / 256.f);
    float vs = 0.f;
#pragma unroll
    for (int k = 0; k < 8; k++) { float d = v[k] - mean; vs += d * d; }
#pragma unroll
    for (int o = 16; o; o >>= 1) vs += __shfl_xor_sync(0xffffffffu, vs, o);
    float rstd = rsqrtf(vs * (1.f / 256.f) + 1e-5f);
    const float* xr = x + (size_t)row * D_;
    float* orow = out + (size_t)row * D_;
#pragma unroll
    for (int k = 0; k < 8; k++) {
        int col = lane + 32 * k;
        orow[col] = xr[col] + (v[k] - mean) * rstd * g[col] + b[col];
    }
}

// ---------------- launch ----------------
extern "C" void kernel_launch(void* const* d_in, const int* in_sizes, int n_in,
                              void* d_out, int out_size) {
    const float* x   = (const float*)d_in[0];
    const float* src = (const float*)d_in[1];
    const float* af  = (const float*)d_in[2];
    const float* Wq  = (const float*)d_in[3];
    const float* Wk  = (const float*)d_in[4];
    const float* Wv  = (const float*)d_in[5];
    const float* Wm  = (const float*)d_in[6];
    const float* W1  = (const float*)d_in[7];
    const float* W2  = (const float*)d_in[8];
    const float* g1  = (const float*)d_in[9];
    const float* b1  = (const float*)d_in[10];
    const float* g2  = (const float*)d_in[11];
    const float* b2  = (const float*)d_in[12];
    float* out = (float*)d_out;

    float *Qp, *Kp, *Vp, *Op, *M1p, *Hin, *Hre, *M2p, *pacc, *pml;
    cudaGetSymbolAddress((void**)&Qp,   g_Q);
    cudaGetSymbolAddress((void**)&Kp,   g_K);
    cudaGetSymbolAddress((void**)&Vp,   g_V);
    cudaGetSymbolAddress((void**)&Op,   g_O);
    cudaGetSymbolAddress((void**)&M1p,  g_M1);
    cudaGetSymbolAddress((void**)&Hin,  g_Hin);
    cudaGetSymbolAddress((void**)&Hre,  g_Hre);
    cudaGetSymbolAddress((void**)&M2p,  g_M2);
    cudaGetSymbolAddress((void**)&pacc, g_pacc);
    cudaGetSymbolAddress((void**)&pml,  g_pml);

    const int attn_smem = SMEM_ATTN_FLOATS * (int)sizeof(float);  // ~95.2 KB
    cudaFuncSetAttribute(attn_tc, cudaFuncAttributeMaxDynamicSharedMemorySize, attn_smem);

    // Q/K/V projections: tensor-core, prefetched, tf32-rounded outputs (384 CTAs)
    gemm_qkv_tc<<<dim3(D_ / 64, ROWS / 128, 3), 256>>>(x, src, Wq, Wk, Wv, Qp, Kp, Vp);
    // flash attention: 64q/CTA, head-group split, split-KV (256 CTAs), pipeline
    attn_tc<<<dim3(L_ / QT, B_, NSPLIT * 2), 128, attn_smem>>>(Qp, Kp, Vp, af, pacc, pml);
    attn_combine<<<dim3(L_ / 8, B_ * H_), 256>>>(pacc, pml, Op);
    // message = O @ Wm^T
    gemm_tc<32><<<dim3(D_ / 32, ROWS / 128), 256>>>(Op, Wm, M1p, D_, D_, 0);
    // LN1 + concat [x, ln(message)]
    ln_concat_kernel<<<ROWS / 8, 256>>>(M1p, x, g1, b1, Hin);
    // h = relu(Hin @ W1^T)
    gemm_tc<64><<<dim3(2 * D_ / 64, ROWS / 128), 256>>>(Hin, W1, Hre, 2 * D_, 2 * D_, 1);
    // M2 = h @ W2^T
    gemm_tc<32><<<dim3(D_ / 32, ROWS / 128), 256>>>(Hre, W2, M2p, D_, 2 * D_, 0);
    // out = x + LN2(M2)
    ln_residual_kernel<<<ROWS / 8, 256>>>(M2p, x, g2, b2, out);
}